// round 1
// baseline (speedup 1.0000x reference)
#include <cuda_runtime.h>
#include <math.h>

#define CAMS   6
#define NQ     6400
#define EMBED  256
#define HEADS  8
#define LEVELS 4
#define POINTS 8
#define DEPTH  4
#define DH     32
#define FLEN   14960
#define MROWS  (CAMS * FLEN)   /* 89760 */
#define NOFFAW 768             /* 512 offsets + 256 aw logits */

// ---------------- static device scratch (no allocations allowed) ----------------
__device__ float g_vproj [(size_t)MROWS * EMBED];       // ~92 MB  [c][f][256]
__device__ float g_offaw [(size_t)NQ * NOFFAW];         // ~20 MB  [n][768]
__device__ float g_outcam[(size_t)CAMS * NQ * EMBED];   // ~39 MB  [c][n][256]
__device__ int   g_maskq [CAMS * NQ];
__device__ float g_invcnt[NQ];

// =======================================================================
// GEMM 1: value projection.  C[r=c*FLEN+f][o] = value[f][c][:]@Wv + bv
// Tile 128x64, BK=16, 256 threads, 8x4 per thread.
// =======================================================================
__global__ __launch_bounds__(256) void vproj_kernel(
    const float* __restrict__ value, const float* __restrict__ Wv,
    const float* __restrict__ bv)
{
    __shared__ float As[16][129];
    __shared__ float Bs[16][64];
    const int tid  = threadIdx.x;
    const int row0 = blockIdx.y * 128;
    const int col0 = blockIdx.x * 64;

    const int lrow = tid >> 2;          // 0..63
    const int lkg  = (tid & 3) << 2;    // k offset within 16
    const float* aptr[2];
    bool aval[2];
#pragma unroll
    for (int s = 0; s < 2; s++) {
        int r = row0 + lrow + s * 64;
        aval[s] = (r < MROWS);
        int rc = aval[s] ? r : 0;
        int c = rc / FLEN;
        int f = rc - c * FLEN;
        aptr[s] = value + ((size_t)f * CAMS + c) * EMBED;
    }
    const int bk  = tid >> 4;           // 0..15
    const int bng = (tid & 15) << 2;    // 0..60
    const int ty  = tid >> 4;
    const int tx  = tid & 15;

    float acc[8][4];
#pragma unroll
    for (int i = 0; i < 8; i++)
#pragma unroll
        for (int j = 0; j < 4; j++) acc[i][j] = 0.f;

    for (int k0 = 0; k0 < EMBED; k0 += 16) {
#pragma unroll
        for (int s = 0; s < 2; s++) {
            float4 v = make_float4(0.f, 0.f, 0.f, 0.f);
            if (aval[s]) v = *reinterpret_cast<const float4*>(aptr[s] + k0 + lkg);
            int rr = lrow + s * 64;
            As[lkg + 0][rr] = v.x; As[lkg + 1][rr] = v.y;
            As[lkg + 2][rr] = v.z; As[lkg + 3][rr] = v.w;
        }
        float4 b = *reinterpret_cast<const float4*>(
            Wv + (size_t)(k0 + bk) * EMBED + col0 + bng);
        *reinterpret_cast<float4*>(&Bs[bk][bng]) = b;
        __syncthreads();
#pragma unroll
        for (int k = 0; k < 16; k++) {
            float a[8], bb[4];
#pragma unroll
            for (int i = 0; i < 8; i++) a[i] = As[k][ty + 16 * i];
#pragma unroll
            for (int j = 0; j < 4; j++) bb[j] = Bs[k][tx + 16 * j];
#pragma unroll
            for (int i = 0; i < 8; i++)
#pragma unroll
                for (int j = 0; j < 4; j++) acc[i][j] += a[i] * bb[j];
        }
        __syncthreads();
    }
#pragma unroll
    for (int i = 0; i < 8; i++) {
        int r = row0 + ty + 16 * i;
        if (r >= MROWS) continue;
#pragma unroll
        for (int j = 0; j < 4; j++) {
            int n = col0 + tx + 16 * j;
            g_vproj[(size_t)r * EMBED + n] = acc[i][j] + bv[n];
        }
    }
}

// =======================================================================
// GEMM 2: offsets + aw logits.  A = query+query_pos (6400x256),
// B = [Wso | Waw] (256x768).  Cam-independent!
// =======================================================================
__global__ __launch_bounds__(256) void offaw_kernel(
    const float* __restrict__ query, const float* __restrict__ qpos,
    const float* __restrict__ Wso, const float* __restrict__ bso,
    const float* __restrict__ Waw, const float* __restrict__ baw)
{
    __shared__ float As[16][129];
    __shared__ float Bs[16][64];
    const int tid  = threadIdx.x;
    const int row0 = blockIdx.y * 128;
    const int col0 = blockIdx.x * 64;
    const bool is_so   = (col0 < 512);
    const float* Bbase = is_so ? Wso : Waw;
    const int bstride  = is_so ? 512 : 256;
    const int bcol     = is_so ? col0 : (col0 - 512);

    const int lrow = tid >> 2;
    const int lkg  = (tid & 3) << 2;
    const int bk   = tid >> 4;
    const int bng  = (tid & 15) << 2;
    const int ty   = tid >> 4;
    const int tx   = tid & 15;

    float acc[8][4];
#pragma unroll
    for (int i = 0; i < 8; i++)
#pragma unroll
        for (int j = 0; j < 4; j++) acc[i][j] = 0.f;

    for (int k0 = 0; k0 < EMBED; k0 += 16) {
#pragma unroll
        for (int s = 0; s < 2; s++) {
            int r = row0 + lrow + s * 64;
            float4 a = *reinterpret_cast<const float4*>(query + (size_t)r * EMBED + k0 + lkg);
            float4 p = *reinterpret_cast<const float4*>(qpos  + (size_t)r * EMBED + k0 + lkg);
            int rr = lrow + s * 64;
            As[lkg + 0][rr] = a.x + p.x; As[lkg + 1][rr] = a.y + p.y;
            As[lkg + 2][rr] = a.z + p.z; As[lkg + 3][rr] = a.w + p.w;
        }
        float4 b = *reinterpret_cast<const float4*>(
            Bbase + (size_t)(k0 + bk) * bstride + bcol + bng);
        *reinterpret_cast<float4*>(&Bs[bk][bng]) = b;
        __syncthreads();
#pragma unroll
        for (int k = 0; k < 16; k++) {
            float a[8], bb[4];
#pragma unroll
            for (int i = 0; i < 8; i++) a[i] = As[k][ty + 16 * i];
#pragma unroll
            for (int j = 0; j < 4; j++) bb[j] = Bs[k][tx + 16 * j];
#pragma unroll
            for (int i = 0; i < 8; i++)
#pragma unroll
                for (int j = 0; j < 4; j++) acc[i][j] += a[i] * bb[j];
        }
        __syncthreads();
    }
#pragma unroll
    for (int i = 0; i < 8; i++) {
        int r = row0 + ty + 16 * i;
#pragma unroll
        for (int j = 0; j < 4; j++) {
            int col  = col0 + tx + 16 * j;
            float bias = (col < 512) ? bso[col] : baw[col - 512];
            g_offaw[(size_t)r * NOFFAW + col] = acc[i][j] + bias;
        }
    }
}

// =======================================================================
// mask / count:   maskq[c][n] = any_d(bev_mask[c,0,n,d]); invcnt[n]
// bev_mask read as 4-byte words: nonzero test works for int32 and fp32 0/1.
// =======================================================================
__global__ void mask_kernel(const unsigned int* __restrict__ bm)
{
    int n = blockIdx.x * blockDim.x + threadIdx.x;
    if (n >= NQ) return;
    int cnt = 0;
#pragma unroll
    for (int c = 0; c < CAMS; c++) {
        const unsigned int* q = bm + ((size_t)c * NQ + n) * DEPTH;
        unsigned int any = q[0] | q[1] | q[2] | q[3];
        int m = any ? 1 : 0;
        g_maskq[c * NQ + n] = m;
        cnt += m;
    }
    g_invcnt[n] = 1.0f / fmaxf((float)cnt, 1.0f);
}

// =======================================================================
// softmax over the 32 aw logits per (n, h), in place on g_offaw[:,512:768]
// one warp per (n,h), 8 warps / block
// =======================================================================
__global__ __launch_bounds__(256) void softmax_kernel()
{
    int g    = blockIdx.x * 8 + (threadIdx.x >> 5);
    int lane = threadIdx.x & 31;
    int n = g >> 3;          // g / HEADS
    int h = g & 7;
    float* p = g_offaw + (size_t)n * NOFFAW + 512 + h * 32;
    float v = p[lane];
    float m = v;
#pragma unroll
    for (int o = 16; o; o >>= 1) m = fmaxf(m, __shfl_xor_sync(0xffffffffu, m, o));
    float e = __expf(v - m);
    float s = e;
#pragma unroll
    for (int o = 16; o; o >>= 1) s += __shfl_xor_sync(0xffffffffu, s, o);
    p[lane] = e / s;
}

// =======================================================================
// MSDA sampler: one block per (cam, n). 8 warps = 8 heads; within a warp,
// the 32 lanes are the 32 channels of the head; loop 32 samples (l,p).
// Inactive (masked) pairs write zeros and exit.
// =======================================================================
__global__ __launch_bounds__(256) void sampler_kernel(const float* __restrict__ refcam)
{
    const int bx = blockIdx.x;           // c*NQ + n
    const int c  = bx / NQ;
    const int n  = bx - c * NQ;
    __shared__ float soff[512];
    __shared__ float saw[256];
    __shared__ float sref[8];
    __shared__ int   smask;

    const int tid = threadIdx.x;
    if (tid == 0) smask = g_maskq[bx];
    soff[tid]       = g_offaw[(size_t)n * NOFFAW + tid];
    soff[tid + 256] = g_offaw[(size_t)n * NOFFAW + 256 + tid];
    saw[tid]        = g_offaw[(size_t)n * NOFFAW + 512 + tid];
    if (tid < 8) sref[tid] = refcam[(size_t)bx * 8 + tid];
    __syncthreads();

    float acc = 0.f;
    if (smask) {
        const int h    = tid >> 5;
        const int lane = tid & 31;
        const int   cWl[4] = {176, 88, 44, 22};
        const int   cHl[4] = {64, 32, 16, 8};
        const int   cls[4] = {0, 11264, 14080, 14784};
        const float* vb = g_vproj + (size_t)c * FLEN * EMBED + h * DH + lane;
#pragma unroll
        for (int s = 0; s < 32; s++) {
            const int l = s >> 3;
            const int p = s & 7;
            const int d = p & 3;
            const int Wl = cWl[l], Hl = cHl[l], ls = cls[l];
            float x = sref[d * 2 + 0] * (float)Wl + soff[((h * 4 + l) * 8 + p) * 2 + 0] - 0.5f;
            float y = sref[d * 2 + 1] * (float)Hl + soff[((h * 4 + l) * 8 + p) * 2 + 1] - 0.5f;
            float a = saw[h * 32 + s];
            float x0f = floorf(x), y0f = floorf(y);
            float fx = x - x0f, fy = y - y0f;
            int x0 = (int)x0f, y0 = (int)y0f;
            float w00 = (1.f - fx) * (1.f - fy) * a;
            float w10 = fx * (1.f - fy) * a;
            float w01 = (1.f - fx) * fy * a;
            float w11 = fx * fy * a;
            if ((unsigned)x0 < (unsigned)Wl && (unsigned)y0 < (unsigned)Hl)
                acc += w00 * vb[(size_t)(ls + y0 * Wl + x0) * EMBED];
            if ((unsigned)(x0 + 1) < (unsigned)Wl && (unsigned)y0 < (unsigned)Hl)
                acc += w10 * vb[(size_t)(ls + y0 * Wl + x0 + 1) * EMBED];
            if ((unsigned)x0 < (unsigned)Wl && (unsigned)(y0 + 1) < (unsigned)Hl)
                acc += w01 * vb[(size_t)(ls + (y0 + 1) * Wl + x0) * EMBED];
            if ((unsigned)(x0 + 1) < (unsigned)Wl && (unsigned)(y0 + 1) < (unsigned)Hl)
                acc += w11 * vb[(size_t)(ls + (y0 + 1) * Wl + x0 + 1) * EMBED];
        }
    }
    g_outcam[(size_t)bx * EMBED + tid] = acc;
}

// =======================================================================
// GEMM 3 (final): A[r][k] = invcnt[r] * sum_c outcam[c][r][k];
// out = A @ Wout + bout + query   (residual fused)
// =======================================================================
__global__ __launch_bounds__(256) void final_kernel(
    const float* __restrict__ query, const float* __restrict__ Wout,
    const float* __restrict__ bout, float* __restrict__ out)
{
    __shared__ float As[16][129];
    __shared__ float Bs[16][64];
    const int tid  = threadIdx.x;
    const int row0 = blockIdx.y * 128;
    const int col0 = blockIdx.x * 64;

    const int lrow = tid >> 2;
    const int lkg  = (tid & 3) << 2;
    const int bk   = tid >> 4;
    const int bng  = (tid & 15) << 2;
    const int ty   = tid >> 4;
    const int tx   = tid & 15;

    float inv[2];
#pragma unroll
    for (int s = 0; s < 2; s++) inv[s] = g_invcnt[row0 + lrow + s * 64];

    float acc[8][4];
#pragma unroll
    for (int i = 0; i < 8; i++)
#pragma unroll
        for (int j = 0; j < 4; j++) acc[i][j] = 0.f;

    for (int k0 = 0; k0 < EMBED; k0 += 16) {
#pragma unroll
        for (int s = 0; s < 2; s++) {
            int r = row0 + lrow + s * 64;
            float4 sum = make_float4(0.f, 0.f, 0.f, 0.f);
#pragma unroll
            for (int c = 0; c < CAMS; c++) {
                float4 v = *reinterpret_cast<const float4*>(
                    g_outcam + ((size_t)c * NQ + r) * EMBED + k0 + lkg);
                sum.x += v.x; sum.y += v.y; sum.z += v.z; sum.w += v.w;
            }
            int rr = lrow + s * 64;
            As[lkg + 0][rr] = sum.x * inv[s];
            As[lkg + 1][rr] = sum.y * inv[s];
            As[lkg + 2][rr] = sum.z * inv[s];
            As[lkg + 3][rr] = sum.w * inv[s];
        }
        float4 b = *reinterpret_cast<const float4*>(
            Wout + (size_t)(k0 + bk) * EMBED + col0 + bng);
        *reinterpret_cast<float4*>(&Bs[bk][bng]) = b;
        __syncthreads();
#pragma unroll
        for (int k = 0; k < 16; k++) {
            float a[8], bb[4];
#pragma unroll
            for (int i = 0; i < 8; i++) a[i] = As[k][ty + 16 * i];
#pragma unroll
            for (int j = 0; j < 4; j++) bb[j] = Bs[k][tx + 16 * j];
#pragma unroll
            for (int i = 0; i < 8; i++)
#pragma unroll
                for (int j = 0; j < 4; j++) acc[i][j] += a[i] * bb[j];
        }
        __syncthreads();
    }
#pragma unroll
    for (int i = 0; i < 8; i++) {
        int r = row0 + ty + 16 * i;
#pragma unroll
        for (int j = 0; j < 4; j++) {
            int n = col0 + tx + 16 * j;
            out[(size_t)r * EMBED + n] = acc[i][j] + bout[n] + query[(size_t)r * EMBED + n];
        }
    }
}

// =======================================================================
extern "C" void kernel_launch(void* const* d_in, const int* in_sizes, int n_in,
                              void* d_out, int out_size)
{
    const float* query = (const float*)d_in[0];
    /* d_in[1] = key : unused by the reference */
    const float* value = (const float*)d_in[2];
    const float* qpos  = (const float*)d_in[3];
    const float* refc  = (const float*)d_in[4];
    const unsigned int* bmask = (const unsigned int*)d_in[5];
    /* d_in[6] spatial_shapes, d_in[7] level_start_index : compile-time constants */
    const float* Wv   = (const float*)d_in[8];
    const float* bv   = (const float*)d_in[9];
    const float* Wso  = (const float*)d_in[10];
    const float* bso  = (const float*)d_in[11];
    const float* Waw  = (const float*)d_in[12];
    const float* baw  = (const float*)d_in[13];
    const float* Wout = (const float*)d_in[14];
    const float* bout = (const float*)d_in[15];
    float* out = (float*)d_out;

    vproj_kernel  <<<dim3(4, 702), 256>>>(value, Wv, bv);
    offaw_kernel  <<<dim3(12, 50), 256>>>(query, qpos, Wso, bso, Waw, baw);
    mask_kernel   <<<25, 256>>>(bmask);
    softmax_kernel<<<6400, 256>>>();
    sampler_kernel<<<CAMS * NQ, 256>>>(refc);
    final_kernel  <<<dim3(4, 50), 256>>>(query, Wout, bout, out);
}

// round 4
// speedup vs baseline: 2.2176x; 2.2176x over previous
#include <cuda_runtime.h>
#include <cuda_bf16.h>
#include <cstdint>
#include <stdint.h>
#include <math.h>

#define CAMS   6
#define NQ     6400
#define EMBED  256
#define HEADS  8
#define LEVELS 4
#define POINTS 8
#define DEPTH  4
#define DH     32
#define FLEN   14960
#define MROWS  (CAMS * FLEN)   /* 89760 */
#define NOFFAW 768             /* 512 offsets + 256 aw logits */

// ---------------- static device scratch (no allocations allowed) ----------------
__device__ float g_vproj [(size_t)MROWS * EMBED];       // ~92 MB  [c][f][256]
__device__ float g_offaw [(size_t)NQ * NOFFAW];         // ~20 MB  [n][768]
__device__ float g_outcam[(size_t)CAMS * NQ * EMBED];   // ~39 MB  [c][n][256]
__device__ int   g_maskq [CAMS * NQ];
__device__ float g_invcnt[NQ];

// =======================================================================
// GEMM 1 (mma.sync bf16): vproj[r][n] = value_row(r) @ Wv[:, n] + bv[n]
// CTA tile 128(M) x 128(N), K=256. 8 warps (4M x 2N), warp tile 32x64.
// B (= Wv^T, [n][k] bf16) fully resident in smem; A converted per 32-k chunk.
// =======================================================================
#define BP 264                 /* Bs pitch in bf16 (256 + 8) */
#define AP 40                  /* As pitch in bf16 (32 + 8)  */
#define VP_SMEM (128 * BP * 2 + 128 * AP * 2)   /* 67584 + 10240 = 77824 B */

__device__ __forceinline__ void mma_bf16(float* c, const uint32_t* a, const uint32_t* b)
{
    asm volatile(
        "mma.sync.aligned.m16n8k16.row.col.f32.bf16.bf16.f32 "
        "{%0,%1,%2,%3}, {%4,%5,%6,%7}, {%8,%9}, {%0,%1,%2,%3};"
        : "+f"(c[0]), "+f"(c[1]), "+f"(c[2]), "+f"(c[3])
        : "r"(a[0]), "r"(a[1]), "r"(a[2]), "r"(a[3]), "r"(b[0]), "r"(b[1]));
}

__global__ __launch_bounds__(256) void vproj_mma_kernel(
    const float* __restrict__ value, const float* __restrict__ Wv,
    const float* __restrict__ bv)
{
    extern __shared__ char smem[];
    __nv_bfloat16* Bs = reinterpret_cast<__nv_bfloat16*>(smem);
    __nv_bfloat16* As = reinterpret_cast<__nv_bfloat16*>(smem + 128 * BP * 2);

    const int tid  = threadIdx.x;
    const int wid  = tid >> 5;
    const int lane = tid & 31;
    const int wm   = wid >> 1;          // 0..3
    const int wn   = wid & 1;           // 0..1
    const int n0   = blockIdx.x * 128;  // 0 or 128
    const int row0 = blockIdx.y * 128;

    // ---- load B = Wv^T into smem ([n][k], bf16) ----
#pragma unroll
    for (int i = 0; i < 64; i++) {
        int u  = i * 256 + tid;         // 0..16383
        int k  = u >> 6;                // 0..255
        int np = u & 63;                // n pair
        float2 w = *reinterpret_cast<const float2*>(Wv + (size_t)k * EMBED + n0 + np * 2);
        Bs[(np * 2 + 0) * BP + k] = __float2bfloat16(w.x);
        Bs[(np * 2 + 1) * BP + k] = __float2bfloat16(w.y);
    }

    float acc[2][8][4];
#pragma unroll
    for (int mi = 0; mi < 2; mi++)
#pragma unroll
        for (int ni = 0; ni < 8; ni++)
#pragma unroll
            for (int j = 0; j < 4; j++) acc[mi][ni][j] = 0.f;

    const int qr = lane >> 2;           // 0..7
    const int qc = lane & 3;            // 0..3

    for (int kc = 0; kc < 8; kc++) {
        __syncthreads();
        // ---- A chunk: 128 rows x 32 k, fp32 -> bf16 ----
#pragma unroll
        for (int i = 0; i < 4; i++) {
            int u   = i * 256 + tid;    // 0..1023
            int row = u >> 3;
            int kq  = (u & 7) * 4;
            int r = row0 + row;
            if (r >= MROWS) r = MROWS - 1;
            int c = r / FLEN;
            int f = r - c * FLEN;
            float4 v = *reinterpret_cast<const float4*>(
                value + ((size_t)f * CAMS + c) * EMBED + kc * 32 + kq);
            __nv_bfloat162 p0, p1;
            p0.x = __float2bfloat16(v.x); p0.y = __float2bfloat16(v.y);
            p1.x = __float2bfloat16(v.z); p1.y = __float2bfloat16(v.w);
            uint2 st;
            st.x = *reinterpret_cast<uint32_t*>(&p0);
            st.y = *reinterpret_cast<uint32_t*>(&p1);
            *reinterpret_cast<uint2*>(&As[row * AP + kq]) = st;
        }
        __syncthreads();

#pragma unroll
        for (int ks = 0; ks < 32; ks += 16) {
            uint32_t a[2][4], b[8][2];
#pragma unroll
            for (int mi = 0; mi < 2; mi++) {
                int rb = wm * 32 + mi * 16;
                a[mi][0] = *reinterpret_cast<const uint32_t*>(&As[(rb + qr)     * AP + ks + qc * 2]);
                a[mi][1] = *reinterpret_cast<const uint32_t*>(&As[(rb + qr + 8) * AP + ks + qc * 2]);
                a[mi][2] = *reinterpret_cast<const uint32_t*>(&As[(rb + qr)     * AP + ks + qc * 2 + 8]);
                a[mi][3] = *reinterpret_cast<const uint32_t*>(&As[(rb + qr + 8) * AP + ks + qc * 2 + 8]);
            }
#pragma unroll
            for (int ni = 0; ni < 8; ni++) {
                int nn = wn * 64 + ni * 8 + qr;
                b[ni][0] = *reinterpret_cast<const uint32_t*>(&Bs[nn * BP + kc * 32 + ks + qc * 2]);
                b[ni][1] = *reinterpret_cast<const uint32_t*>(&Bs[nn * BP + kc * 32 + ks + qc * 2 + 8]);
            }
#pragma unroll
            for (int mi = 0; mi < 2; mi++)
#pragma unroll
                for (int ni = 0; ni < 8; ni++)
                    mma_bf16(acc[mi][ni], a[mi], b[ni]);
        }
    }

    // ---- epilogue: fp32 + bias -> g_vproj ----
#pragma unroll
    for (int mi = 0; mi < 2; mi++) {
        int rb = row0 + wm * 32 + mi * 16;
#pragma unroll
        for (int half = 0; half < 2; half++) {
            int r = rb + qr + half * 8;
            if (r >= MROWS) continue;
            float* dst = g_vproj + (size_t)r * EMBED;
#pragma unroll
            for (int ni = 0; ni < 8; ni++) {
                int n = n0 + wn * 64 + ni * 8 + qc * 2;
                float2 o;
                o.x = acc[mi][ni][half * 2 + 0] + bv[n];
                o.y = acc[mi][ni][half * 2 + 1] + bv[n + 1];
                *reinterpret_cast<float2*>(dst + n) = o;
            }
        }
    }
}

// =======================================================================
// GEMM 2: offsets + aw logits.  A = query+query_pos (6400x256),
// B = [Wso | Waw] (256x768).  Cam-independent!
// =======================================================================
__global__ __launch_bounds__(256) void offaw_kernel(
    const float* __restrict__ query, const float* __restrict__ qpos,
    const float* __restrict__ Wso, const float* __restrict__ bso,
    const float* __restrict__ Waw, const float* __restrict__ baw)
{
    __shared__ float As[16][129];
    __shared__ float Bs[16][64];
    const int tid  = threadIdx.x;
    const int row0 = blockIdx.y * 128;
    const int col0 = blockIdx.x * 64;
    const bool is_so   = (col0 < 512);
    const float* Bbase = is_so ? Wso : Waw;
    const int bstride  = is_so ? 512 : 256;
    const int bcol     = is_so ? col0 : (col0 - 512);

    const int lrow = tid >> 2;
    const int lkg  = (tid & 3) << 2;
    const int bk   = tid >> 4;
    const int bng  = (tid & 15) << 2;
    const int ty   = tid >> 4;
    const int tx   = tid & 15;

    float acc[8][4];
#pragma unroll
    for (int i = 0; i < 8; i++)
#pragma unroll
        for (int j = 0; j < 4; j++) acc[i][j] = 0.f;

    for (int k0 = 0; k0 < EMBED; k0 += 16) {
#pragma unroll
        for (int s = 0; s < 2; s++) {
            int r = row0 + lrow + s * 64;
            float4 a = *reinterpret_cast<const float4*>(query + (size_t)r * EMBED + k0 + lkg);
            float4 p = *reinterpret_cast<const float4*>(qpos  + (size_t)r * EMBED + k0 + lkg);
            int rr = lrow + s * 64;
            As[lkg + 0][rr] = a.x + p.x; As[lkg + 1][rr] = a.y + p.y;
            As[lkg + 2][rr] = a.z + p.z; As[lkg + 3][rr] = a.w + p.w;
        }
        float4 b = *reinterpret_cast<const float4*>(
            Bbase + (size_t)(k0 + bk) * bstride + bcol + bng);
        *reinterpret_cast<float4*>(&Bs[bk][bng]) = b;
        __syncthreads();
#pragma unroll
        for (int k = 0; k < 16; k++) {
            float a[8], bb[4];
#pragma unroll
            for (int i = 0; i < 8; i++) a[i] = As[k][ty + 16 * i];
#pragma unroll
            for (int j = 0; j < 4; j++) bb[j] = Bs[k][tx + 16 * j];
#pragma unroll
            for (int i = 0; i < 8; i++)
#pragma unroll
                for (int j = 0; j < 4; j++) acc[i][j] += a[i] * bb[j];
        }
        __syncthreads();
    }
#pragma unroll
    for (int i = 0; i < 8; i++) {
        int r = row0 + ty + 16 * i;
#pragma unroll
        for (int j = 0; j < 4; j++) {
            int col  = col0 + tx + 16 * j;
            float bias = (col < 512) ? bso[col] : baw[col - 512];
            g_offaw[(size_t)r * NOFFAW + col] = acc[i][j] + bias;
        }
    }
}

// =======================================================================
// mask / count
// =======================================================================
__global__ void mask_kernel(const unsigned int* __restrict__ bm)
{
    int n = blockIdx.x * blockDim.x + threadIdx.x;
    if (n >= NQ) return;
    int cnt = 0;
#pragma unroll
    for (int c = 0; c < CAMS; c++) {
        const unsigned int* q = bm + ((size_t)c * NQ + n) * DEPTH;
        unsigned int any = q[0] | q[1] | q[2] | q[3];
        int m = any ? 1 : 0;
        g_maskq[c * NQ + n] = m;
        cnt += m;
    }
    g_invcnt[n] = 1.0f / fmaxf((float)cnt, 1.0f);
}

// =======================================================================
// softmax over the 32 aw logits per (n, h)
// =======================================================================
__global__ __launch_bounds__(256) void softmax_kernel()
{
    int g    = blockIdx.x * 8 + (threadIdx.x >> 5);
    int lane = threadIdx.x & 31;
    int n = g >> 3;
    int h = g & 7;
    float* p = g_offaw + (size_t)n * NOFFAW + 512 + h * 32;
    float v = p[lane];
    float m = v;
#pragma unroll
    for (int o = 16; o; o >>= 1) m = fmaxf(m, __shfl_xor_sync(0xffffffffu, m, o));
    float e = __expf(v - m);
    float s = e;
#pragma unroll
    for (int o = 16; o; o >>= 1) s += __shfl_xor_sync(0xffffffffu, s, o);
    p[lane] = e / s;
}

// =======================================================================
// MSDA sampler
// =======================================================================
__global__ __launch_bounds__(256) void sampler_kernel(const float* __restrict__ refcam)
{
    const int bx = blockIdx.x;           // c*NQ + n
    const int c  = bx / NQ;
    const int n  = bx - c * NQ;
    __shared__ float soff[512];
    __shared__ float saw[256];
    __shared__ float sref[8];
    __shared__ int   smask;

    const int tid = threadIdx.x;
    if (tid == 0) smask = g_maskq[bx];
    soff[tid]       = g_offaw[(size_t)n * NOFFAW + tid];
    soff[tid + 256] = g_offaw[(size_t)n * NOFFAW + 256 + tid];
    saw[tid]        = g_offaw[(size_t)n * NOFFAW + 512 + tid];
    if (tid < 8) sref[tid] = refcam[(size_t)bx * 8 + tid];
    __syncthreads();

    float acc = 0.f;
    if (smask) {
        const int h    = tid >> 5;
        const int lane = tid & 31;
        const int   cWl[4] = {176, 88, 44, 22};
        const int   cHl[4] = {64, 32, 16, 8};
        const int   cls[4] = {0, 11264, 14080, 14784};
        const float* vb = g_vproj + (size_t)c * FLEN * EMBED + h * DH + lane;
#pragma unroll
        for (int s = 0; s < 32; s++) {
            const int l = s >> 3;
            const int p = s & 7;
            const int d = p & 3;
            const int Wl = cWl[l], Hl = cHl[l], ls = cls[l];
            float x = sref[d * 2 + 0] * (float)Wl + soff[((h * 4 + l) * 8 + p) * 2 + 0] - 0.5f;
            float y = sref[d * 2 + 1] * (float)Hl + soff[((h * 4 + l) * 8 + p) * 2 + 1] - 0.5f;
            float a = saw[h * 32 + s];
            float x0f = floorf(x), y0f = floorf(y);
            float fx = x - x0f, fy = y - y0f;
            int x0 = (int)x0f, y0 = (int)y0f;
            float w00 = (1.f - fx) * (1.f - fy) * a;
            float w10 = fx * (1.f - fy) * a;
            float w01 = (1.f - fx) * fy * a;
            float w11 = fx * fy * a;
            if ((unsigned)x0 < (unsigned)Wl && (unsigned)y0 < (unsigned)Hl)
                acc += w00 * vb[(size_t)(ls + y0 * Wl + x0) * EMBED];
            if ((unsigned)(x0 + 1) < (unsigned)Wl && (unsigned)y0 < (unsigned)Hl)
                acc += w10 * vb[(size_t)(ls + y0 * Wl + x0 + 1) * EMBED];
            if ((unsigned)x0 < (unsigned)Wl && (unsigned)(y0 + 1) < (unsigned)Hl)
                acc += w01 * vb[(size_t)(ls + (y0 + 1) * Wl + x0) * EMBED];
            if ((unsigned)(x0 + 1) < (unsigned)Wl && (unsigned)(y0 + 1) < (unsigned)Hl)
                acc += w11 * vb[(size_t)(ls + (y0 + 1) * Wl + x0 + 1) * EMBED];
        }
    }
    g_outcam[(size_t)bx * EMBED + tid] = acc;
}

// =======================================================================
// GEMM 3 (final)
// =======================================================================
__global__ __launch_bounds__(256) void final_kernel(
    const float* __restrict__ query, const float* __restrict__ Wout,
    const float* __restrict__ bout, float* __restrict__ out)
{
    __shared__ float As[16][129];
    __shared__ float Bs[16][64];
    const int tid  = threadIdx.x;
    const int row0 = blockIdx.y * 128;
    const int col0 = blockIdx.x * 64;

    const int lrow = tid >> 2;
    const int lkg  = (tid & 3) << 2;
    const int bk   = tid >> 4;
    const int bng  = (tid & 15) << 2;
    const int ty   = tid >> 4;
    const int tx   = tid & 15;

    float inv[2];
#pragma unroll
    for (int s = 0; s < 2; s++) inv[s] = g_invcnt[row0 + lrow + s * 64];

    float acc[8][4];
#pragma unroll
    for (int i = 0; i < 8; i++)
#pragma unroll
        for (int j = 0; j < 4; j++) acc[i][j] = 0.f;

    for (int k0 = 0; k0 < EMBED; k0 += 16) {
#pragma unroll
        for (int s = 0; s < 2; s++) {
            int r = row0 + lrow + s * 64;
            float4 sum = make_float4(0.f, 0.f, 0.f, 0.f);
#pragma unroll
            for (int c = 0; c < CAMS; c++) {
                float4 v = *reinterpret_cast<const float4*>(
                    g_outcam + ((size_t)c * NQ + r) * EMBED + k0 + lkg);
                sum.x += v.x; sum.y += v.y; sum.z += v.z; sum.w += v.w;
            }
            int rr = lrow + s * 64;
            As[lkg + 0][rr] = sum.x * inv[s];
            As[lkg + 1][rr] = sum.y * inv[s];
            As[lkg + 2][rr] = sum.z * inv[s];
            As[lkg + 3][rr] = sum.w * inv[s];
        }
        float4 b = *reinterpret_cast<const float4*>(
            Wout + (size_t)(k0 + bk) * EMBED + col0 + bng);
        *reinterpret_cast<float4*>(&Bs[bk][bng]) = b;
        __syncthreads();
#pragma unroll
        for (int k = 0; k < 16; k++) {
            float a[8], bb[4];
#pragma unroll
            for (int i = 0; i < 8; i++) a[i] = As[k][ty + 16 * i];
#pragma unroll
            for (int j = 0; j < 4; j++) bb[j] = Bs[k][tx + 16 * j];
#pragma unroll
            for (int i = 0; i < 8; i++)
#pragma unroll
                for (int j = 0; j < 4; j++) acc[i][j] += a[i] * bb[j];
        }
        __syncthreads();
    }
#pragma unroll
    for (int i = 0; i < 8; i++) {
        int r = row0 + ty + 16 * i;
#pragma unroll
        for (int j = 0; j < 4; j++) {
            int n = col0 + tx + 16 * j;
            out[(size_t)r * EMBED + n] = acc[i][j] + bout[n] + query[(size_t)r * EMBED + n];
        }
    }
}

// =======================================================================
extern "C" void kernel_launch(void* const* d_in, const int* in_sizes, int n_in,
                              void* d_out, int out_size)
{
    const float* query = (const float*)d_in[0];
    /* d_in[1] = key : unused by the reference */
    const float* value = (const float*)d_in[2];
    const float* qpos  = (const float*)d_in[3];
    const float* refc  = (const float*)d_in[4];
    const unsigned int* bmask = (const unsigned int*)d_in[5];
    /* d_in[6] spatial_shapes, d_in[7] level_start_index : compile-time constants */
    const float* Wv   = (const float*)d_in[8];
    const float* bv   = (const float*)d_in[9];
    const float* Wso  = (const float*)d_in[10];
    const float* bso  = (const float*)d_in[11];
    const float* Waw  = (const float*)d_in[12];
    const float* baw  = (const float*)d_in[13];
    const float* Wout = (const float*)d_in[14];
    const float* bout = (const float*)d_in[15];
    float* out = (float*)d_out;

    cudaFuncSetAttribute(vproj_mma_kernel,
                         cudaFuncAttributeMaxDynamicSharedMemorySize, VP_SMEM);

    vproj_mma_kernel<<<dim3(2, 702), 256, VP_SMEM>>>(value, Wv, bv);
    offaw_kernel    <<<dim3(12, 50), 256>>>(query, qpos, Wso, bso, Waw, baw);
    mask_kernel     <<<25, 256>>>(bmask);
    softmax_kernel  <<<6400, 256>>>();
    sampler_kernel  <<<CAMS * NQ, 256>>>(refc);
    final_kernel    <<<dim3(4, 50), 256>>>(query, Wout, bout, out);
}

// round 5
// speedup vs baseline: 2.8165x; 1.2701x over previous
#include <cuda_runtime.h>
#include <cuda_bf16.h>
#include <cstdint>
#include <stdint.h>
#include <math.h>

#define CAMS   6
#define NQ     6400
#define EMBED  256
#define HEADS  8
#define LEVELS 4
#define POINTS 8
#define DEPTH  4
#define DH     32
#define FLEN   14960
#define MROWS  (CAMS * FLEN)   /* 89760 */
#define NOFFAW 768             /* 512 offsets + 256 aw logits */

// ---------------- static device scratch (no allocations allowed) ----------------
__device__ __nv_bfloat16 g_vproj [(size_t)MROWS * EMBED];      // ~46 MB  [c][f][256]
__device__ float         g_offaw [(size_t)NQ * NOFFAW];        // ~20 MB  [n][768]
__device__ __nv_bfloat16 g_outcam[(size_t)CAMS * NQ * EMBED];  // ~20 MB  [c][n][256]
__device__ int   g_maskq [CAMS * NQ];
__device__ float g_invcnt[NQ];

// ======================== shared mma tile machinery =====================
#define BP 264                 /* Bs pitch in bf16 (256 + 8) */
#define AP 40                  /* As pitch in bf16 (32 + 8)  */
#define VP_SMEM (128 * BP * 2 + 128 * AP * 2)   /* 77824 B */

__device__ __forceinline__ void mma_bf16(float* c, const uint32_t* a, const uint32_t* b)
{
    asm volatile(
        "mma.sync.aligned.m16n8k16.row.col.f32.bf16.bf16.f32 "
        "{%0,%1,%2,%3}, {%4,%5,%6,%7}, {%8,%9}, {%0,%1,%2,%3};"
        : "+f"(c[0]), "+f"(c[1]), "+f"(c[2]), "+f"(c[3])
        : "r"(a[0]), "r"(a[1]), "r"(a[2]), "r"(a[3]), "r"(b[0]), "r"(b[1]));
}

// inner-loop body shared by all three GEMMs (Bs fully resident, As chunked)
__device__ __forceinline__ void mma_chunk(
    const __nv_bfloat16* As, const __nv_bfloat16* Bs, int kc,
    int wm, int wn, int qr, int qc, float acc[2][8][4])
{
#pragma unroll
    for (int ks = 0; ks < 32; ks += 16) {
        uint32_t a[2][4], b[8][2];
#pragma unroll
        for (int mi = 0; mi < 2; mi++) {
            int rb = wm * 32 + mi * 16;
            a[mi][0] = *reinterpret_cast<const uint32_t*>(&As[(rb + qr)     * AP + ks + qc * 2]);
            a[mi][1] = *reinterpret_cast<const uint32_t*>(&As[(rb + qr + 8) * AP + ks + qc * 2]);
            a[mi][2] = *reinterpret_cast<const uint32_t*>(&As[(rb + qr)     * AP + ks + qc * 2 + 8]);
            a[mi][3] = *reinterpret_cast<const uint32_t*>(&As[(rb + qr + 8) * AP + ks + qc * 2 + 8]);
        }
#pragma unroll
        for (int ni = 0; ni < 8; ni++) {
            int nn = wn * 64 + ni * 8 + qr;
            b[ni][0] = *reinterpret_cast<const uint32_t*>(&Bs[nn * BP + kc * 32 + ks + qc * 2]);
            b[ni][1] = *reinterpret_cast<const uint32_t*>(&Bs[nn * BP + kc * 32 + ks + qc * 2 + 8]);
        }
#pragma unroll
        for (int mi = 0; mi < 2; mi++)
#pragma unroll
            for (int ni = 0; ni < 8; ni++)
                mma_bf16(acc[mi][ni], a[mi], b[ni]);
    }
}

// =======================================================================
// GEMM 1: vproj[r][n] = value_row(r) @ Wv[:, n] + bv[n]  (bf16 out)
// =======================================================================
__global__ __launch_bounds__(256) void vproj_mma_kernel(
    const float* __restrict__ value, const float* __restrict__ Wv,
    const float* __restrict__ bv)
{
    extern __shared__ char smem[];
    __nv_bfloat16* Bs = reinterpret_cast<__nv_bfloat16*>(smem);
    __nv_bfloat16* As = reinterpret_cast<__nv_bfloat16*>(smem + 128 * BP * 2);

    const int tid  = threadIdx.x;
    const int wid  = tid >> 5;
    const int lane = tid & 31;
    const int wm   = wid >> 1;
    const int wn   = wid & 1;
    const int n0   = blockIdx.x * 128;
    const int row0 = blockIdx.y * 128;
    const int qr = lane >> 2, qc = lane & 3;

#pragma unroll
    for (int i = 0; i < 64; i++) {
        int u  = i * 256 + tid;
        int k  = u >> 6;
        int np = u & 63;
        float2 w = *reinterpret_cast<const float2*>(Wv + (size_t)k * EMBED + n0 + np * 2);
        Bs[(np * 2 + 0) * BP + k] = __float2bfloat16(w.x);
        Bs[(np * 2 + 1) * BP + k] = __float2bfloat16(w.y);
    }

    float acc[2][8][4];
#pragma unroll
    for (int mi = 0; mi < 2; mi++)
#pragma unroll
        for (int ni = 0; ni < 8; ni++)
#pragma unroll
            for (int j = 0; j < 4; j++) acc[mi][ni][j] = 0.f;

    for (int kc = 0; kc < 8; kc++) {
        __syncthreads();
#pragma unroll
        for (int i = 0; i < 4; i++) {
            int u   = i * 256 + tid;
            int row = u >> 3;
            int kq  = (u & 7) * 4;
            int r = row0 + row;
            if (r >= MROWS) r = MROWS - 1;
            int c = r / FLEN;
            int f = r - c * FLEN;
            float4 v = *reinterpret_cast<const float4*>(
                value + ((size_t)f * CAMS + c) * EMBED + kc * 32 + kq);
            __nv_bfloat162 p0, p1;
            p0.x = __float2bfloat16(v.x); p0.y = __float2bfloat16(v.y);
            p1.x = __float2bfloat16(v.z); p1.y = __float2bfloat16(v.w);
            uint2 st;
            st.x = *reinterpret_cast<uint32_t*>(&p0);
            st.y = *reinterpret_cast<uint32_t*>(&p1);
            *reinterpret_cast<uint2*>(&As[row * AP + kq]) = st;
        }
        __syncthreads();
        mma_chunk(As, Bs, kc, wm, wn, qr, qc, acc);
    }

#pragma unroll
    for (int mi = 0; mi < 2; mi++) {
        int rb = row0 + wm * 32 + mi * 16;
#pragma unroll
        for (int half = 0; half < 2; half++) {
            int r = rb + qr + half * 8;
            if (r >= MROWS) continue;
            __nv_bfloat16* dst = g_vproj + (size_t)r * EMBED;
#pragma unroll
            for (int ni = 0; ni < 8; ni++) {
                int n = n0 + wn * 64 + ni * 8 + qc * 2;
                __nv_bfloat162 o;
                o.x = __float2bfloat16(acc[mi][ni][half * 2 + 0] + bv[n]);
                o.y = __float2bfloat16(acc[mi][ni][half * 2 + 1] + bv[n + 1]);
                *reinterpret_cast<__nv_bfloat162*>(dst + n) = o;
            }
        }
    }
}

// =======================================================================
// GEMM 2: offaw[r][col] = (query+qpos)(r,:) @ [Wso|Waw](:,col) + bias
// M=6400, N=768, K=256
// =======================================================================
__global__ __launch_bounds__(256) void offaw_mma_kernel(
    const float* __restrict__ query, const float* __restrict__ qpos,
    const float* __restrict__ Wso, const float* __restrict__ bso,
    const float* __restrict__ Waw, const float* __restrict__ baw)
{
    extern __shared__ char smem[];
    __nv_bfloat16* Bs = reinterpret_cast<__nv_bfloat16*>(smem);
    __nv_bfloat16* As = reinterpret_cast<__nv_bfloat16*>(smem + 128 * BP * 2);

    const int tid  = threadIdx.x;
    const int wid  = tid >> 5;
    const int lane = tid & 31;
    const int wm   = wid >> 1;
    const int wn   = wid & 1;
    const int n0   = blockIdx.x * 128;        // 0..640
    const int row0 = blockIdx.y * 128;
    const int qr = lane >> 2, qc = lane & 3;

    const bool is_so   = (n0 < 512);
    const float* Bsrc  = is_so ? Wso : Waw;
    const int    bstr  = is_so ? 512 : 256;
    const int    bcol0 = is_so ? n0 : (n0 - 512);

#pragma unroll
    for (int i = 0; i < 64; i++) {
        int u  = i * 256 + tid;
        int k  = u >> 6;
        int np = u & 63;
        float2 w = *reinterpret_cast<const float2*>(Bsrc + (size_t)k * bstr + bcol0 + np * 2);
        Bs[(np * 2 + 0) * BP + k] = __float2bfloat16(w.x);
        Bs[(np * 2 + 1) * BP + k] = __float2bfloat16(w.y);
    }

    float acc[2][8][4];
#pragma unroll
    for (int mi = 0; mi < 2; mi++)
#pragma unroll
        for (int ni = 0; ni < 8; ni++)
#pragma unroll
            for (int j = 0; j < 4; j++) acc[mi][ni][j] = 0.f;

    for (int kc = 0; kc < 8; kc++) {
        __syncthreads();
#pragma unroll
        for (int i = 0; i < 4; i++) {
            int u   = i * 256 + tid;
            int row = u >> 3;
            int kq  = (u & 7) * 4;
            int r = row0 + row;
            float4 a = *reinterpret_cast<const float4*>(query + (size_t)r * EMBED + kc * 32 + kq);
            float4 p = *reinterpret_cast<const float4*>(qpos  + (size_t)r * EMBED + kc * 32 + kq);
            __nv_bfloat162 p0, p1;
            p0.x = __float2bfloat16(a.x + p.x); p0.y = __float2bfloat16(a.y + p.y);
            p1.x = __float2bfloat16(a.z + p.z); p1.y = __float2bfloat16(a.w + p.w);
            uint2 st;
            st.x = *reinterpret_cast<uint32_t*>(&p0);
            st.y = *reinterpret_cast<uint32_t*>(&p1);
            *reinterpret_cast<uint2*>(&As[row * AP + kq]) = st;
        }
        __syncthreads();
        mma_chunk(As, Bs, kc, wm, wn, qr, qc, acc);
    }

#pragma unroll
    for (int mi = 0; mi < 2; mi++) {
        int rb = row0 + wm * 32 + mi * 16;
#pragma unroll
        for (int half = 0; half < 2; half++) {
            int r = rb + qr + half * 8;
            float* dst = g_offaw + (size_t)r * NOFFAW;
#pragma unroll
            for (int ni = 0; ni < 8; ni++) {
                int col = n0 + wn * 64 + ni * 8 + qc * 2;
                float b0 = (col < 512) ? bso[col] : baw[col - 512];
                float b1 = (col + 1 < 512) ? bso[col + 1] : baw[col + 1 - 512];
                float2 o;
                o.x = acc[mi][ni][half * 2 + 0] + b0;
                o.y = acc[mi][ni][half * 2 + 1] + b1;
                *reinterpret_cast<float2*>(dst + col) = o;
            }
        }
    }
}

// =======================================================================
// mask / count
// =======================================================================
__global__ void mask_kernel(const unsigned int* __restrict__ bm)
{
    int n = blockIdx.x * blockDim.x + threadIdx.x;
    if (n >= NQ) return;
    int cnt = 0;
#pragma unroll
    for (int c = 0; c < CAMS; c++) {
        const unsigned int* q = bm + ((size_t)c * NQ + n) * DEPTH;
        unsigned int any = q[0] | q[1] | q[2] | q[3];
        int m = any ? 1 : 0;
        g_maskq[c * NQ + n] = m;
        cnt += m;
    }
    g_invcnt[n] = 1.0f / fmaxf((float)cnt, 1.0f);
}

// =======================================================================
// softmax over the 32 aw logits per (n, h)
// =======================================================================
__global__ __launch_bounds__(256) void softmax_kernel()
{
    int g    = blockIdx.x * 8 + (threadIdx.x >> 5);
    int lane = threadIdx.x & 31;
    int n = g >> 3;
    int h = g & 7;
    float* p = g_offaw + (size_t)n * NOFFAW + 512 + h * 32;
    float v = p[lane];
    float m = v;
#pragma unroll
    for (int o = 16; o; o >>= 1) m = fmaxf(m, __shfl_xor_sync(0xffffffffu, m, o));
    float e = __expf(v - m);
    float s = e;
#pragma unroll
    for (int o = 16; o; o >>= 1) s += __shfl_xor_sync(0xffffffffu, s, o);
    p[lane] = e / s;
}

// =======================================================================
// MSDA sampler (bf16 value gather, masked blocks exit early)
// =======================================================================
__global__ __launch_bounds__(256) void sampler_kernel(const float* __restrict__ refcam)
{
    const int bx = blockIdx.x;           // c*NQ + n
    const int c  = bx / NQ;
    const int n  = bx - c * NQ;
    __shared__ float soff[512];
    __shared__ float saw[256];
    __shared__ float sref[8];
    __shared__ int   smask;

    const int tid = threadIdx.x;
    if (tid == 0) smask = g_maskq[bx];
    __syncthreads();
    if (!smask) {
        g_outcam[(size_t)bx * EMBED + tid] = __float2bfloat16(0.f);
        return;
    }

    soff[tid]       = g_offaw[(size_t)n * NOFFAW + tid];
    soff[tid + 256] = g_offaw[(size_t)n * NOFFAW + 256 + tid];
    saw[tid]        = g_offaw[(size_t)n * NOFFAW + 512 + tid];
    if (tid < 8) sref[tid] = refcam[(size_t)bx * 8 + tid];
    __syncthreads();

    float acc = 0.f;
    {
        const int h    = tid >> 5;
        const int lane = tid & 31;
        const int   cWl[4] = {176, 88, 44, 22};
        const int   cHl[4] = {64, 32, 16, 8};
        const int   cls[4] = {0, 11264, 14080, 14784};
        const __nv_bfloat16* vb = g_vproj + (size_t)c * FLEN * EMBED + h * DH + lane;
#pragma unroll
        for (int s = 0; s < 32; s++) {
            const int l = s >> 3;
            const int p = s & 7;
            const int d = p & 3;
            const int Wl = cWl[l], Hl = cHl[l], ls = cls[l];
            float x = sref[d * 2 + 0] * (float)Wl + soff[((h * 4 + l) * 8 + p) * 2 + 0] - 0.5f;
            float y = sref[d * 2 + 1] * (float)Hl + soff[((h * 4 + l) * 8 + p) * 2 + 1] - 0.5f;
            float a = saw[h * 32 + s];
            float x0f = floorf(x), y0f = floorf(y);
            float fx = x - x0f, fy = y - y0f;
            int x0 = (int)x0f, y0 = (int)y0f;
            float w00 = (1.f - fx) * (1.f - fy) * a;
            float w10 = fx * (1.f - fy) * a;
            float w01 = (1.f - fx) * fy * a;
            float w11 = fx * fy * a;
            if ((unsigned)x0 < (unsigned)Wl && (unsigned)y0 < (unsigned)Hl)
                acc += w00 * __bfloat162float(vb[(size_t)(ls + y0 * Wl + x0) * EMBED]);
            if ((unsigned)(x0 + 1) < (unsigned)Wl && (unsigned)y0 < (unsigned)Hl)
                acc += w10 * __bfloat162float(vb[(size_t)(ls + y0 * Wl + x0 + 1) * EMBED]);
            if ((unsigned)x0 < (unsigned)Wl && (unsigned)(y0 + 1) < (unsigned)Hl)
                acc += w01 * __bfloat162float(vb[(size_t)(ls + (y0 + 1) * Wl + x0) * EMBED]);
            if ((unsigned)(x0 + 1) < (unsigned)Wl && (unsigned)(y0 + 1) < (unsigned)Hl)
                acc += w11 * __bfloat162float(vb[(size_t)(ls + (y0 + 1) * Wl + x0 + 1) * EMBED]);
        }
    }
    g_outcam[(size_t)bx * EMBED + tid] = __float2bfloat16(acc);
}

// =======================================================================
// GEMM 3 (final mma): A[r][k] = invcnt[r]*sum_c outcam[c][r][k] (bf16)
// out = A @ Wout + bout + query.  M=6400, N=256, K=256.
// =======================================================================
__global__ __launch_bounds__(256) void final_mma_kernel(
    const float* __restrict__ query, const float* __restrict__ Wout,
    const float* __restrict__ bout, float* __restrict__ out)
{
    extern __shared__ char smem[];
    __nv_bfloat16* Bs = reinterpret_cast<__nv_bfloat16*>(smem);
    __nv_bfloat16* As = reinterpret_cast<__nv_bfloat16*>(smem + 128 * BP * 2);

    const int tid  = threadIdx.x;
    const int wid  = tid >> 5;
    const int lane = tid & 31;
    const int wm   = wid >> 1;
    const int wn   = wid & 1;
    const int n0   = blockIdx.x * 128;
    const int row0 = blockIdx.y * 128;
    const int qr = lane >> 2, qc = lane & 3;

#pragma unroll
    for (int i = 0; i < 64; i++) {
        int u  = i * 256 + tid;
        int k  = u >> 6;
        int np = u & 63;
        float2 w = *reinterpret_cast<const float2*>(Wout + (size_t)k * EMBED + n0 + np * 2);
        Bs[(np * 2 + 0) * BP + k] = __float2bfloat16(w.x);
        Bs[(np * 2 + 1) * BP + k] = __float2bfloat16(w.y);
    }

    float acc[2][8][4];
#pragma unroll
    for (int mi = 0; mi < 2; mi++)
#pragma unroll
        for (int ni = 0; ni < 8; ni++)
#pragma unroll
            for (int j = 0; j < 4; j++) acc[mi][ni][j] = 0.f;

    for (int kc = 0; kc < 8; kc++) {
        __syncthreads();
#pragma unroll
        for (int i = 0; i < 4; i++) {
            int u   = i * 256 + tid;
            int row = u >> 3;
            int kq  = (u & 7) * 4;
            int r = row0 + row;
            float inv = g_invcnt[r];
            float s0 = 0.f, s1 = 0.f, s2 = 0.f, s3 = 0.f;
#pragma unroll
            for (int c = 0; c < CAMS; c++) {
                const __nv_bfloat16* src =
                    g_outcam + ((size_t)c * NQ + r) * EMBED + kc * 32 + kq;
                uint2 u2 = *reinterpret_cast<const uint2*>(src);
                __nv_bfloat162 p0 = *reinterpret_cast<__nv_bfloat162*>(&u2.x);
                __nv_bfloat162 p1 = *reinterpret_cast<__nv_bfloat162*>(&u2.y);
                s0 += __bfloat162float(p0.x); s1 += __bfloat162float(p0.y);
                s2 += __bfloat162float(p1.x); s3 += __bfloat162float(p1.y);
            }
            __nv_bfloat162 q0, q1;
            q0.x = __float2bfloat16(s0 * inv); q0.y = __float2bfloat16(s1 * inv);
            q1.x = __float2bfloat16(s2 * inv); q1.y = __float2bfloat16(s3 * inv);
            uint2 st;
            st.x = *reinterpret_cast<uint32_t*>(&q0);
            st.y = *reinterpret_cast<uint32_t*>(&q1);
            *reinterpret_cast<uint2*>(&As[row * AP + kq]) = st;
        }
        __syncthreads();
        mma_chunk(As, Bs, kc, wm, wn, qr, qc, acc);
    }

#pragma unroll
    for (int mi = 0; mi < 2; mi++) {
        int rb = row0 + wm * 32 + mi * 16;
#pragma unroll
        for (int half = 0; half < 2; half++) {
            int r = rb + qr + half * 8;
            float* dst = out + (size_t)r * EMBED;
            const float* qsrc = query + (size_t)r * EMBED;
#pragma unroll
            for (int ni = 0; ni < 8; ni++) {
                int n = n0 + wn * 64 + ni * 8 + qc * 2;
                float2 qv = *reinterpret_cast<const float2*>(qsrc + n);
                float2 o;
                o.x = acc[mi][ni][half * 2 + 0] + bout[n] + qv.x;
                o.y = acc[mi][ni][half * 2 + 1] + bout[n + 1] + qv.y;
                *reinterpret_cast<float2*>(dst + n) = o;
            }
        }
    }
}

// =======================================================================
extern "C" void kernel_launch(void* const* d_in, const int* in_sizes, int n_in,
                              void* d_out, int out_size)
{
    const float* query = (const float*)d_in[0];
    /* d_in[1] = key : unused by the reference */
    const float* value = (const float*)d_in[2];
    const float* qpos  = (const float*)d_in[3];
    const float* refc  = (const float*)d_in[4];
    const unsigned int* bmask = (const unsigned int*)d_in[5];
    /* d_in[6] spatial_shapes, d_in[7] level_start_index : compile-time constants */
    const float* Wv   = (const float*)d_in[8];
    const float* bv   = (const float*)d_in[9];
    const float* Wso  = (const float*)d_in[10];
    const float* bso  = (const float*)d_in[11];
    const float* Waw  = (const float*)d_in[12];
    const float* baw  = (const float*)d_in[13];
    const float* Wout = (const float*)d_in[14];
    const float* bout = (const float*)d_in[15];
    float* out = (float*)d_out;

    cudaFuncSetAttribute(vproj_mma_kernel,
                         cudaFuncAttributeMaxDynamicSharedMemorySize, VP_SMEM);
    cudaFuncSetAttribute(offaw_mma_kernel,
                         cudaFuncAttributeMaxDynamicSharedMemorySize, VP_SMEM);
    cudaFuncSetAttribute(final_mma_kernel,
                         cudaFuncAttributeMaxDynamicSharedMemorySize, VP_SMEM);

    vproj_mma_kernel<<<dim3(2, 702), 256, VP_SMEM>>>(value, Wv, bv);
    offaw_mma_kernel<<<dim3(6, 50), 256, VP_SMEM>>>(query, qpos, Wso, bso, Waw, baw);
    mask_kernel     <<<25, 256>>>(bmask);
    softmax_kernel  <<<6400, 256>>>();
    sampler_kernel  <<<CAMS * NQ, 256>>>(refc);
    final_mma_kernel<<<dim3(2, 50), 256, VP_SMEM>>>(query, Wout, bout, out);
}

// round 6
// speedup vs baseline: 3.5290x; 1.2530x over previous
#include <cuda_runtime.h>
#include <cuda_bf16.h>
#include <cstdint>
#include <stdint.h>
#include <math.h>

#define CAMS   6
#define NQ     6400
#define EMBED  256
#define HEADS  8
#define LEVELS 4
#define POINTS 8
#define DEPTH  4
#define DH     32
#define FLEN   14960
#define MROWS  (CAMS * FLEN)   /* 89760 */
#define NOFFAW 768             /* 512 offsets + 256 aw logits */

// ---------------- static device scratch (no allocations allowed) ----------------
__device__ __nv_bfloat16 g_vproj [(size_t)MROWS * EMBED];      // ~46 MB  [c][f][256]
__device__ float         g_offaw [(size_t)NQ * NOFFAW];        // ~20 MB  [n][768]
__device__ __nv_bfloat16 g_outcam[(size_t)CAMS * NQ * EMBED];  // ~20 MB  [c][n][256]
__device__ int   g_maskq [CAMS * NQ];
__device__ float g_invcnt[NQ];

// ======================== shared mma tile machinery =====================
#define BP 264                 /* Bs pitch in bf16 (256 + 8) */
#define AP 40                  /* As pitch in bf16 (32 + 8)  */
#define VP_SMEM (128 * BP * 2 + 128 * AP * 2)   /* 77824 B */

__device__ __forceinline__ void mma_bf16(float* c, const uint32_t* a, const uint32_t* b)
{
    asm volatile(
        "mma.sync.aligned.m16n8k16.row.col.f32.bf16.bf16.f32 "
        "{%0,%1,%2,%3}, {%4,%5,%6,%7}, {%8,%9}, {%0,%1,%2,%3};"
        : "+f"(c[0]), "+f"(c[1]), "+f"(c[2]), "+f"(c[3])
        : "r"(a[0]), "r"(a[1]), "r"(a[2]), "r"(a[3]), "r"(b[0]), "r"(b[1]));
}

// inner-loop body shared by all three GEMMs (Bs fully resident, As chunked)
__device__ __forceinline__ void mma_chunk(
    const __nv_bfloat16* As, const __nv_bfloat16* Bs, int kc,
    int wm, int wn, int qr, int qc, float acc[2][8][4])
{
#pragma unroll
    for (int ks = 0; ks < 32; ks += 16) {
        uint32_t a[2][4], b[8][2];
#pragma unroll
        for (int mi = 0; mi < 2; mi++) {
            int rb = wm * 32 + mi * 16;
            a[mi][0] = *reinterpret_cast<const uint32_t*>(&As[(rb + qr)     * AP + ks + qc * 2]);
            a[mi][1] = *reinterpret_cast<const uint32_t*>(&As[(rb + qr + 8) * AP + ks + qc * 2]);
            a[mi][2] = *reinterpret_cast<const uint32_t*>(&As[(rb + qr)     * AP + ks + qc * 2 + 8]);
            a[mi][3] = *reinterpret_cast<const uint32_t*>(&As[(rb + qr + 8) * AP + ks + qc * 2 + 8]);
        }
#pragma unroll
        for (int ni = 0; ni < 8; ni++) {
            int nn = wn * 64 + ni * 8 + qr;
            b[ni][0] = *reinterpret_cast<const uint32_t*>(&Bs[nn * BP + kc * 32 + ks + qc * 2]);
            b[ni][1] = *reinterpret_cast<const uint32_t*>(&Bs[nn * BP + kc * 32 + ks + qc * 2 + 8]);
        }
#pragma unroll
        for (int mi = 0; mi < 2; mi++)
#pragma unroll
            for (int ni = 0; ni < 8; ni++)
                mma_bf16(acc[mi][ni], a[mi], b[ni]);
    }
}

// =======================================================================
// GEMM 1: vproj[r][n] = value_row(r) @ Wv[:, n] + bv[n]  (bf16 out)
// =======================================================================
__global__ __launch_bounds__(256) void vproj_mma_kernel(
    const float* __restrict__ value, const float* __restrict__ Wv,
    const float* __restrict__ bv)
{
    extern __shared__ char smem[];
    __nv_bfloat16* Bs = reinterpret_cast<__nv_bfloat16*>(smem);
    __nv_bfloat16* As = reinterpret_cast<__nv_bfloat16*>(smem + 128 * BP * 2);

    const int tid  = threadIdx.x;
    const int wid  = tid >> 5;
    const int lane = tid & 31;
    const int wm   = wid >> 1;
    const int wn   = wid & 1;
    const int n0   = blockIdx.x * 128;
    const int row0 = blockIdx.y * 128;
    const int qr = lane >> 2, qc = lane & 3;

#pragma unroll
    for (int i = 0; i < 64; i++) {
        int u  = i * 256 + tid;
        int k  = u >> 6;
        int np = u & 63;
        float2 w = *reinterpret_cast<const float2*>(Wv + (size_t)k * EMBED + n0 + np * 2);
        Bs[(np * 2 + 0) * BP + k] = __float2bfloat16(w.x);
        Bs[(np * 2 + 1) * BP + k] = __float2bfloat16(w.y);
    }

    float acc[2][8][4];
#pragma unroll
    for (int mi = 0; mi < 2; mi++)
#pragma unroll
        for (int ni = 0; ni < 8; ni++)
#pragma unroll
            for (int j = 0; j < 4; j++) acc[mi][ni][j] = 0.f;

    for (int kc = 0; kc < 8; kc++) {
        __syncthreads();
#pragma unroll
        for (int i = 0; i < 4; i++) {
            int u   = i * 256 + tid;
            int row = u >> 3;
            int kq  = (u & 7) * 4;
            int r = row0 + row;
            if (r >= MROWS) r = MROWS - 1;
            int c = r / FLEN;
            int f = r - c * FLEN;
            float4 v = *reinterpret_cast<const float4*>(
                value + ((size_t)f * CAMS + c) * EMBED + kc * 32 + kq);
            __nv_bfloat162 p0, p1;
            p0.x = __float2bfloat16(v.x); p0.y = __float2bfloat16(v.y);
            p1.x = __float2bfloat16(v.z); p1.y = __float2bfloat16(v.w);
            uint2 st;
            st.x = *reinterpret_cast<uint32_t*>(&p0);
            st.y = *reinterpret_cast<uint32_t*>(&p1);
            *reinterpret_cast<uint2*>(&As[row * AP + kq]) = st;
        }
        __syncthreads();
        mma_chunk(As, Bs, kc, wm, wn, qr, qc, acc);
    }

#pragma unroll
    for (int mi = 0; mi < 2; mi++) {
        int rb = row0 + wm * 32 + mi * 16;
#pragma unroll
        for (int half = 0; half < 2; half++) {
            int r = rb + qr + half * 8;
            if (r >= MROWS) continue;
            __nv_bfloat16* dst = g_vproj + (size_t)r * EMBED;
#pragma unroll
            for (int ni = 0; ni < 8; ni++) {
                int n = n0 + wn * 64 + ni * 8 + qc * 2;
                __nv_bfloat162 o;
                o.x = __float2bfloat16(acc[mi][ni][half * 2 + 0] + bv[n]);
                o.y = __float2bfloat16(acc[mi][ni][half * 2 + 1] + bv[n + 1]);
                *reinterpret_cast<__nv_bfloat162*>(dst + n) = o;
            }
        }
    }
}

// =======================================================================
// GEMM 2: offaw[r][col] = (query+qpos)(r,:) @ [Wso|Waw](:,col) + bias
// =======================================================================
__global__ __launch_bounds__(256) void offaw_mma_kernel(
    const float* __restrict__ query, const float* __restrict__ qpos,
    const float* __restrict__ Wso, const float* __restrict__ bso,
    const float* __restrict__ Waw, const float* __restrict__ baw)
{
    extern __shared__ char smem[];
    __nv_bfloat16* Bs = reinterpret_cast<__nv_bfloat16*>(smem);
    __nv_bfloat16* As = reinterpret_cast<__nv_bfloat16*>(smem + 128 * BP * 2);

    const int tid  = threadIdx.x;
    const int wid  = tid >> 5;
    const int lane = tid & 31;
    const int wm   = wid >> 1;
    const int wn   = wid & 1;
    const int n0   = blockIdx.x * 128;        // 0..640
    const int row0 = blockIdx.y * 128;
    const int qr = lane >> 2, qc = lane & 3;

    const bool is_so   = (n0 < 512);
    const float* Bsrc  = is_so ? Wso : Waw;
    const int    bstr  = is_so ? 512 : 256;
    const int    bcol0 = is_so ? n0 : (n0 - 512);

#pragma unroll
    for (int i = 0; i < 64; i++) {
        int u  = i * 256 + tid;
        int k  = u >> 6;
        int np = u & 63;
        float2 w = *reinterpret_cast<const float2*>(Bsrc + (size_t)k * bstr + bcol0 + np * 2);
        Bs[(np * 2 + 0) * BP + k] = __float2bfloat16(w.x);
        Bs[(np * 2 + 1) * BP + k] = __float2bfloat16(w.y);
    }

    float acc[2][8][4];
#pragma unroll
    for (int mi = 0; mi < 2; mi++)
#pragma unroll
        for (int ni = 0; ni < 8; ni++)
#pragma unroll
            for (int j = 0; j < 4; j++) acc[mi][ni][j] = 0.f;

    for (int kc = 0; kc < 8; kc++) {
        __syncthreads();
#pragma unroll
        for (int i = 0; i < 4; i++) {
            int u   = i * 256 + tid;
            int row = u >> 3;
            int kq  = (u & 7) * 4;
            int r = row0 + row;
            float4 a = *reinterpret_cast<const float4*>(query + (size_t)r * EMBED + kc * 32 + kq);
            float4 p = *reinterpret_cast<const float4*>(qpos  + (size_t)r * EMBED + kc * 32 + kq);
            __nv_bfloat162 p0, p1;
            p0.x = __float2bfloat16(a.x + p.x); p0.y = __float2bfloat16(a.y + p.y);
            p1.x = __float2bfloat16(a.z + p.z); p1.y = __float2bfloat16(a.w + p.w);
            uint2 st;
            st.x = *reinterpret_cast<uint32_t*>(&p0);
            st.y = *reinterpret_cast<uint32_t*>(&p1);
            *reinterpret_cast<uint2*>(&As[row * AP + kq]) = st;
        }
        __syncthreads();
        mma_chunk(As, Bs, kc, wm, wn, qr, qc, acc);
    }

#pragma unroll
    for (int mi = 0; mi < 2; mi++) {
        int rb = row0 + wm * 32 + mi * 16;
#pragma unroll
        for (int half = 0; half < 2; half++) {
            int r = rb + qr + half * 8;
            float* dst = g_offaw + (size_t)r * NOFFAW;
#pragma unroll
            for (int ni = 0; ni < 8; ni++) {
                int col = n0 + wn * 64 + ni * 8 + qc * 2;
                float b0 = (col < 512) ? bso[col] : baw[col - 512];
                float b1 = (col + 1 < 512) ? bso[col + 1] : baw[col + 1 - 512];
                float2 o;
                o.x = acc[mi][ni][half * 2 + 0] + b0;
                o.y = acc[mi][ni][half * 2 + 1] + b1;
                *reinterpret_cast<float2*>(dst + col) = o;
            }
        }
    }
}

// =======================================================================
// mask / count
// =======================================================================
__global__ void mask_kernel(const unsigned int* __restrict__ bm)
{
    int n = blockIdx.x * blockDim.x + threadIdx.x;
    if (n >= NQ) return;
    int cnt = 0;
#pragma unroll
    for (int c = 0; c < CAMS; c++) {
        const unsigned int* q = bm + ((size_t)c * NQ + n) * DEPTH;
        unsigned int any = q[0] | q[1] | q[2] | q[3];
        int m = any ? 1 : 0;
        g_maskq[c * NQ + n] = m;
        cnt += m;
    }
    g_invcnt[n] = 1.0f / fmaxf((float)cnt, 1.0f);
}

// =======================================================================
// softmax over the 32 aw logits per (n, h)
// =======================================================================
__global__ __launch_bounds__(256) void softmax_kernel()
{
    int g    = blockIdx.x * 8 + (threadIdx.x >> 5);
    int lane = threadIdx.x & 31;
    int n = g >> 3;
    int h = g & 7;
    float* p = g_offaw + (size_t)n * NOFFAW + 512 + h * 32;
    float v = p[lane];
    float m = v;
#pragma unroll
    for (int o = 16; o; o >>= 1) m = fmaxf(m, __shfl_xor_sync(0xffffffffu, m, o));
    float e = __expf(v - m);
    float s = e;
#pragma unroll
    for (int o = 16; o; o >>= 1) s += __shfl_xor_sync(0xffffffffu, s, o);
    p[lane] = e / s;
}

// =======================================================================
// MSDA sampler, two-phase:
//  phase1: 256 threads each compute one (head, sample) -> 4 clamped indices
//          + 4 weights (0 when out-of-bounds) into smem
//  phase2: warp h loops 32 samples: broadcast LDS + 4 unpredicated LDG + FMA
// =======================================================================
__global__ __launch_bounds__(256) void sampler_kernel(const float* __restrict__ refcam)
{
    const int bx = blockIdx.x;           // c*NQ + n
    const int c  = bx / NQ;
    const int n  = bx - c * NQ;
    __shared__ float sref[8];
    __shared__ int   smask;
    __shared__ int4   sidx[256];
    __shared__ float4 swt [256];

    const int tid = threadIdx.x;
    if (tid == 0) smask = g_maskq[bx];
    if (tid < 8) sref[tid] = refcam[(size_t)bx * 8 + tid];
    __syncthreads();
    if (!smask) {
        g_outcam[(size_t)bx * EMBED + tid] = __float2bfloat16(0.f);
        return;
    }

    // ---- phase 1: coordinates & weights ----
    {
        const int s = tid & 31;          // sample within head
        const int l = s >> 3;
        const int d = s & 3;             // p & 3 == s & 3
        const int   cWl[4] = {176, 88, 44, 22};
        const int   cHl[4] = {64, 32, 16, 8};
        const int   cls[4] = {0, 11264, 14080, 14784};
        const int Wl = cWl[l], Hl = cHl[l], ls = cls[l];

        float2 off = *reinterpret_cast<const float2*>(g_offaw + (size_t)n * NOFFAW + 2 * tid);
        float  aw  = g_offaw[(size_t)n * NOFFAW + 512 + tid];

        float x = sref[d * 2 + 0] * (float)Wl + off.x - 0.5f;
        float y = sref[d * 2 + 1] * (float)Hl + off.y - 0.5f;
        float x0f = floorf(x), y0f = floorf(y);
        float fx = x - x0f, fy = y - y0f;
        int x0 = (int)x0f, y0 = (int)y0f;
        int x1 = x0 + 1,   y1 = y0 + 1;

        float vx0 = ((unsigned)x0 < (unsigned)Wl) ? 1.f : 0.f;
        float vx1 = ((unsigned)x1 < (unsigned)Wl) ? 1.f : 0.f;
        float vy0 = ((unsigned)y0 < (unsigned)Hl) ? 1.f : 0.f;
        float vy1 = ((unsigned)y1 < (unsigned)Hl) ? 1.f : 0.f;

        int cx0 = min(max(x0, 0), Wl - 1);
        int cx1 = min(max(x1, 0), Wl - 1);
        int cy0 = min(max(y0, 0), Hl - 1);
        int cy1 = min(max(y1, 0), Hl - 1);

        int4 id;
        id.x = ls + cy0 * Wl + cx0;
        id.y = ls + cy0 * Wl + cx1;
        id.z = ls + cy1 * Wl + cx0;
        id.w = ls + cy1 * Wl + cx1;
        float4 w;
        w.x = (1.f - fx) * (1.f - fy) * aw * vx0 * vy0;
        w.y = fx * (1.f - fy) * aw * vx1 * vy0;
        w.z = (1.f - fx) * fy * aw * vx0 * vy1;
        w.w = fx * fy * aw * vx1 * vy1;
        sidx[tid] = id;
        swt [tid] = w;
    }
    __syncthreads();

    // ---- phase 2: gather ----
    {
        const int h    = tid >> 5;
        const int lane = tid & 31;
        const __nv_bfloat16* vb = g_vproj + (size_t)c * FLEN * EMBED + h * DH + lane;
        float acc = 0.f;
#pragma unroll 8
        for (int s = 0; s < 32; s++) {
            int4   id = sidx[h * 32 + s];
            float4 w  = swt [h * 32 + s];
            acc += w.x * __bfloat162float(vb[(size_t)id.x * EMBED]);
            acc += w.y * __bfloat162float(vb[(size_t)id.y * EMBED]);
            acc += w.z * __bfloat162float(vb[(size_t)id.z * EMBED]);
            acc += w.w * __bfloat162float(vb[(size_t)id.w * EMBED]);
        }
        g_outcam[(size_t)bx * EMBED + tid] = __float2bfloat16(acc);
    }
}

// =======================================================================
// GEMM 3 (final mma): A[r][k] = invcnt[r]*sum_c outcam[c][r][k] (bf16)
// out = A @ Wout + bout + query.  M=6400, N=256, K=256.
// =======================================================================
__global__ __launch_bounds__(256) void final_mma_kernel(
    const float* __restrict__ query, const float* __restrict__ Wout,
    const float* __restrict__ bout, float* __restrict__ out)
{
    extern __shared__ char smem[];
    __nv_bfloat16* Bs = reinterpret_cast<__nv_bfloat16*>(smem);
    __nv_bfloat16* As = reinterpret_cast<__nv_bfloat16*>(smem + 128 * BP * 2);

    const int tid  = threadIdx.x;
    const int wid  = tid >> 5;
    const int lane = tid & 31;
    const int wm   = wid >> 1;
    const int wn   = wid & 1;
    const int n0   = blockIdx.x * 128;
    const int row0 = blockIdx.y * 128;
    const int qr = lane >> 2, qc = lane & 3;

#pragma unroll
    for (int i = 0; i < 64; i++) {
        int u  = i * 256 + tid;
        int k  = u >> 6;
        int np = u & 63;
        float2 w = *reinterpret_cast<const float2*>(Wout + (size_t)k * EMBED + n0 + np * 2);
        Bs[(np * 2 + 0) * BP + k] = __float2bfloat16(w.x);
        Bs[(np * 2 + 1) * BP + k] = __float2bfloat16(w.y);
    }

    float acc[2][8][4];
#pragma unroll
    for (int mi = 0; mi < 2; mi++)
#pragma unroll
        for (int ni = 0; ni < 8; ni++)
#pragma unroll
            for (int j = 0; j < 4; j++) acc[mi][ni][j] = 0.f;

    for (int kc = 0; kc < 8; kc++) {
        __syncthreads();
#pragma unroll
        for (int i = 0; i < 4; i++) {
            int u   = i * 256 + tid;
            int row = u >> 3;
            int kq  = (u & 7) * 4;
            int r = row0 + row;
            float inv = g_invcnt[r];
            float s0 = 0.f, s1 = 0.f, s2 = 0.f, s3 = 0.f;
#pragma unroll
            for (int c = 0; c < CAMS; c++) {
                const __nv_bfloat16* src =
                    g_outcam + ((size_t)c * NQ + r) * EMBED + kc * 32 + kq;
                uint2 u2 = *reinterpret_cast<const uint2*>(src);
                __nv_bfloat162 p0 = *reinterpret_cast<__nv_bfloat162*>(&u2.x);
                __nv_bfloat162 p1 = *reinterpret_cast<__nv_bfloat162*>(&u2.y);
                s0 += __bfloat162float(p0.x); s1 += __bfloat162float(p0.y);
                s2 += __bfloat162float(p1.x); s3 += __bfloat162float(p1.y);
            }
            __nv_bfloat162 q0, q1;
            q0.x = __float2bfloat16(s0 * inv); q0.y = __float2bfloat16(s1 * inv);
            q1.x = __float2bfloat16(s2 * inv); q1.y = __float2bfloat16(s3 * inv);
            uint2 st;
            st.x = *reinterpret_cast<uint32_t*>(&q0);
            st.y = *reinterpret_cast<uint32_t*>(&q1);
            *reinterpret_cast<uint2*>(&As[row * AP + kq]) = st;
        }
        __syncthreads();
        mma_chunk(As, Bs, kc, wm, wn, qr, qc, acc);
    }

#pragma unroll
    for (int mi = 0; mi < 2; mi++) {
        int rb = row0 + wm * 32 + mi * 16;
#pragma unroll
        for (int half = 0; half < 2; half++) {
            int r = rb + qr + half * 8;
            float* dst = out + (size_t)r * EMBED;
            const float* qsrc = query + (size_t)r * EMBED;
#pragma unroll
            for (int ni = 0; ni < 8; ni++) {
                int n = n0 + wn * 64 + ni * 8 + qc * 2;
                float2 qv = *reinterpret_cast<const float2*>(qsrc + n);
                float2 o;
                o.x = acc[mi][ni][half * 2 + 0] + bout[n] + qv.x;
                o.y = acc[mi][ni][half * 2 + 1] + bout[n + 1] + qv.y;
                *reinterpret_cast<float2*>(dst + n) = o;
            }
        }
    }
}

// =======================================================================
extern "C" void kernel_launch(void* const* d_in, const int* in_sizes, int n_in,
                              void* d_out, int out_size)
{
    const float* query = (const float*)d_in[0];
    /* d_in[1] = key : unused by the reference */
    const float* value = (const float*)d_in[2];
    const float* qpos  = (const float*)d_in[3];
    const float* refc  = (const float*)d_in[4];
    const unsigned int* bmask = (const unsigned int*)d_in[5];
    /* d_in[6] spatial_shapes, d_in[7] level_start_index : compile-time constants */
    const float* Wv   = (const float*)d_in[8];
    const float* bv   = (const float*)d_in[9];
    const float* Wso  = (const float*)d_in[10];
    const float* bso  = (const float*)d_in[11];
    const float* Waw  = (const float*)d_in[12];
    const float* baw  = (const float*)d_in[13];
    const float* Wout = (const float*)d_in[14];
    const float* bout = (const float*)d_in[15];
    float* out = (float*)d_out;

    cudaFuncSetAttribute(vproj_mma_kernel,
                         cudaFuncAttributeMaxDynamicSharedMemorySize, VP_SMEM);
    cudaFuncSetAttribute(offaw_mma_kernel,
                         cudaFuncAttributeMaxDynamicSharedMemorySize, VP_SMEM);
    cudaFuncSetAttribute(final_mma_kernel,
                         cudaFuncAttributeMaxDynamicSharedMemorySize, VP_SMEM);

    vproj_mma_kernel<<<dim3(2, 702), 256, VP_SMEM>>>(value, Wv, bv);
    offaw_mma_kernel<<<dim3(6, 50), 256, VP_SMEM>>>(query, qpos, Wso, bso, Waw, baw);
    mask_kernel     <<<25, 256>>>(bmask);
    softmax_kernel  <<<6400, 256>>>();
    sampler_kernel  <<<CAMS * NQ, 256>>>(refc);
    final_mma_kernel<<<dim3(2, 50), 256, VP_SMEM>>>(query, Wout, bout, out);
}

// round 7
// speedup vs baseline: 4.1694x; 1.1815x over previous
#include <cuda_runtime.h>
#include <cuda_bf16.h>
#include <cstdint>
#include <stdint.h>
#include <math.h>

#define CAMS   6
#define NQ     6400
#define EMBED  256
#define HEADS  8
#define LEVELS 4
#define POINTS 8
#define DEPTH  4
#define DH     32
#define FLEN   14960
#define MROWS  (CAMS * FLEN)   /* 89760 */
#define NOFFAW 768             /* 512 offsets + 256 aw logits */

// ---------------- static device scratch (no allocations allowed) ----------------
__device__ __nv_bfloat16 g_vproj [(size_t)MROWS * EMBED];      // ~46 MB  [c][f][256]
__device__ float         g_offaw [(size_t)NQ * NOFFAW];        // ~20 MB  [n][768]
__device__ __nv_bfloat16 g_outcam[(size_t)CAMS * NQ * EMBED];  // ~20 MB  [c][n][256]
__device__ int   g_maskq [CAMS * NQ];
__device__ float g_invcnt[NQ];

// ======================== shared mma tile machinery =====================
#define BP 264                 /* Bs pitch in bf16 (256 + 8) */
#define AP 40                  /* As pitch in bf16 (32 + 8)  */
#define VP_SMEM (128 * BP * 2 + 128 * AP * 2)   /* 77824 B */

__device__ __forceinline__ void mma_bf16(float* c, const uint32_t* a, const uint32_t* b)
{
    asm volatile(
        "mma.sync.aligned.m16n8k16.row.col.f32.bf16.bf16.f32 "
        "{%0,%1,%2,%3}, {%4,%5,%6,%7}, {%8,%9}, {%0,%1,%2,%3};"
        : "+f"(c[0]), "+f"(c[1]), "+f"(c[2]), "+f"(c[3])
        : "r"(a[0]), "r"(a[1]), "r"(a[2]), "r"(a[3]), "r"(b[0]), "r"(b[1]));
}

// inner-loop body shared by all three GEMMs (Bs fully resident, As chunked)
__device__ __forceinline__ void mma_chunk(
    const __nv_bfloat16* As, const __nv_bfloat16* Bs, int kc,
    int wm, int wn, int qr, int qc, float acc[2][8][4])
{
#pragma unroll
    for (int ks = 0; ks < 32; ks += 16) {
        uint32_t a[2][4], b[8][2];
#pragma unroll
        for (int mi = 0; mi < 2; mi++) {
            int rb = wm * 32 + mi * 16;
            a[mi][0] = *reinterpret_cast<const uint32_t*>(&As[(rb + qr)     * AP + ks + qc * 2]);
            a[mi][1] = *reinterpret_cast<const uint32_t*>(&As[(rb + qr + 8) * AP + ks + qc * 2]);
            a[mi][2] = *reinterpret_cast<const uint32_t*>(&As[(rb + qr)     * AP + ks + qc * 2 + 8]);
            a[mi][3] = *reinterpret_cast<const uint32_t*>(&As[(rb + qr + 8) * AP + ks + qc * 2 + 8]);
        }
#pragma unroll
        for (int ni = 0; ni < 8; ni++) {
            int nn = wn * 64 + ni * 8 + qr;
            b[ni][0] = *reinterpret_cast<const uint32_t*>(&Bs[nn * BP + kc * 32 + ks + qc * 2]);
            b[ni][1] = *reinterpret_cast<const uint32_t*>(&Bs[nn * BP + kc * 32 + ks + qc * 2 + 8]);
        }
#pragma unroll
        for (int mi = 0; mi < 2; mi++)
#pragma unroll
            for (int ni = 0; ni < 8; ni++)
                mma_bf16(acc[mi][ni], a[mi], b[ni]);
    }
}

// =======================================================================
// GEMM 1: vproj[r][n] = value_row(r) @ Wv[:, n] + bv[n]  (bf16 out)
// Register-prefetch pipeline: next chunk's LDGs issue before mma_chunk.
// =======================================================================
__global__ __launch_bounds__(256) void vproj_mma_kernel(
    const float* __restrict__ value, const float* __restrict__ Wv,
    const float* __restrict__ bv)
{
    extern __shared__ char smem[];
    __nv_bfloat16* Bs = reinterpret_cast<__nv_bfloat16*>(smem);
    __nv_bfloat16* As = reinterpret_cast<__nv_bfloat16*>(smem + 128 * BP * 2);

    const int tid  = threadIdx.x;
    const int wid  = tid >> 5;
    const int lane = tid & 31;
    const int wm   = wid >> 1;
    const int wn   = wid & 1;
    const int n0   = blockIdx.x * 128;
    const int row0 = blockIdx.y * 128;
    const int qr = lane >> 2, qc = lane & 3;

#pragma unroll
    for (int i = 0; i < 64; i++) {
        int u  = i * 256 + tid;
        int k  = u >> 6;
        int np = u & 63;
        float2 w = *reinterpret_cast<const float2*>(Wv + (size_t)k * EMBED + n0 + np * 2);
        Bs[(np * 2 + 0) * BP + k] = __float2bfloat16(w.x);
        Bs[(np * 2 + 1) * BP + k] = __float2bfloat16(w.y);
    }

    // fixed (row, kq) assignment for the A-fill, reused every chunk
    const float* aptr[4];
    int arow[4], akq[4];
#pragma unroll
    for (int i = 0; i < 4; i++) {
        int u   = i * 256 + tid;
        arow[i] = u >> 3;
        akq[i]  = (u & 7) * 4;
        int r = row0 + arow[i];
        if (r >= MROWS) r = MROWS - 1;
        int c = r / FLEN;
        int f = r - c * FLEN;
        aptr[i] = value + ((size_t)f * CAMS + c) * EMBED + akq[i];
    }

    float acc[2][8][4];
#pragma unroll
    for (int mi = 0; mi < 2; mi++)
#pragma unroll
        for (int ni = 0; ni < 8; ni++)
#pragma unroll
            for (int j = 0; j < 4; j++) acc[mi][ni][j] = 0.f;

    float4 v[4];
#pragma unroll
    for (int i = 0; i < 4; i++) v[i] = *reinterpret_cast<const float4*>(aptr[i]);

    for (int kc = 0; kc < 8; kc++) {
        __syncthreads();
#pragma unroll
        for (int i = 0; i < 4; i++) {
            __nv_bfloat162 p0, p1;
            p0.x = __float2bfloat16(v[i].x); p0.y = __float2bfloat16(v[i].y);
            p1.x = __float2bfloat16(v[i].z); p1.y = __float2bfloat16(v[i].w);
            uint2 st;
            st.x = *reinterpret_cast<uint32_t*>(&p0);
            st.y = *reinterpret_cast<uint32_t*>(&p1);
            *reinterpret_cast<uint2*>(&As[arow[i] * AP + akq[i]]) = st;
        }
        __syncthreads();
        if (kc < 7) {
#pragma unroll
            for (int i = 0; i < 4; i++)
                v[i] = *reinterpret_cast<const float4*>(aptr[i] + (kc + 1) * 32);
        }
        mma_chunk(As, Bs, kc, wm, wn, qr, qc, acc);
    }

#pragma unroll
    for (int mi = 0; mi < 2; mi++) {
        int rb = row0 + wm * 32 + mi * 16;
#pragma unroll
        for (int half = 0; half < 2; half++) {
            int r = rb + qr + half * 8;
            if (r >= MROWS) continue;
            __nv_bfloat16* dst = g_vproj + (size_t)r * EMBED;
#pragma unroll
            for (int ni = 0; ni < 8; ni++) {
                int n = n0 + wn * 64 + ni * 8 + qc * 2;
                __nv_bfloat162 o;
                o.x = __float2bfloat16(acc[mi][ni][half * 2 + 0] + bv[n]);
                o.y = __float2bfloat16(acc[mi][ni][half * 2 + 1] + bv[n + 1]);
                *reinterpret_cast<__nv_bfloat162*>(dst + n) = o;
            }
        }
    }
}

// =======================================================================
// GEMM 2: offaw[r][col] = (query+qpos)(r,:) @ [Wso|Waw](:,col) + bias
// =======================================================================
__global__ __launch_bounds__(256) void offaw_mma_kernel(
    const float* __restrict__ query, const float* __restrict__ qpos,
    const float* __restrict__ Wso, const float* __restrict__ bso,
    const float* __restrict__ Waw, const float* __restrict__ baw)
{
    extern __shared__ char smem[];
    __nv_bfloat16* Bs = reinterpret_cast<__nv_bfloat16*>(smem);
    __nv_bfloat16* As = reinterpret_cast<__nv_bfloat16*>(smem + 128 * BP * 2);

    const int tid  = threadIdx.x;
    const int wid  = tid >> 5;
    const int lane = tid & 31;
    const int wm   = wid >> 1;
    const int wn   = wid & 1;
    const int n0   = blockIdx.x * 128;        // 0..640
    const int row0 = blockIdx.y * 128;
    const int qr = lane >> 2, qc = lane & 3;

    const bool is_so   = (n0 < 512);
    const float* Bsrc  = is_so ? Wso : Waw;
    const int    bstr  = is_so ? 512 : 256;
    const int    bcol0 = is_so ? n0 : (n0 - 512);

#pragma unroll
    for (int i = 0; i < 64; i++) {
        int u  = i * 256 + tid;
        int k  = u >> 6;
        int np = u & 63;
        float2 w = *reinterpret_cast<const float2*>(Bsrc + (size_t)k * bstr + bcol0 + np * 2);
        Bs[(np * 2 + 0) * BP + k] = __float2bfloat16(w.x);
        Bs[(np * 2 + 1) * BP + k] = __float2bfloat16(w.y);
    }

    float acc[2][8][4];
#pragma unroll
    for (int mi = 0; mi < 2; mi++)
#pragma unroll
        for (int ni = 0; ni < 8; ni++)
#pragma unroll
            for (int j = 0; j < 4; j++) acc[mi][ni][j] = 0.f;

    for (int kc = 0; kc < 8; kc++) {
        __syncthreads();
#pragma unroll
        for (int i = 0; i < 4; i++) {
            int u   = i * 256 + tid;
            int row = u >> 3;
            int kq  = (u & 7) * 4;
            int r = row0 + row;
            float4 a = *reinterpret_cast<const float4*>(query + (size_t)r * EMBED + kc * 32 + kq);
            float4 p = *reinterpret_cast<const float4*>(qpos  + (size_t)r * EMBED + kc * 32 + kq);
            __nv_bfloat162 p0, p1;
            p0.x = __float2bfloat16(a.x + p.x); p0.y = __float2bfloat16(a.y + p.y);
            p1.x = __float2bfloat16(a.z + p.z); p1.y = __float2bfloat16(a.w + p.w);
            uint2 st;
            st.x = *reinterpret_cast<uint32_t*>(&p0);
            st.y = *reinterpret_cast<uint32_t*>(&p1);
            *reinterpret_cast<uint2*>(&As[row * AP + kq]) = st;
        }
        __syncthreads();
        mma_chunk(As, Bs, kc, wm, wn, qr, qc, acc);
    }

#pragma unroll
    for (int mi = 0; mi < 2; mi++) {
        int rb = row0 + wm * 32 + mi * 16;
#pragma unroll
        for (int half = 0; half < 2; half++) {
            int r = rb + qr + half * 8;
            float* dst = g_offaw + (size_t)r * NOFFAW;
#pragma unroll
            for (int ni = 0; ni < 8; ni++) {
                int col = n0 + wn * 64 + ni * 8 + qc * 2;
                float b0 = (col < 512) ? bso[col] : baw[col - 512];
                float b1 = (col + 1 < 512) ? bso[col + 1] : baw[col + 1 - 512];
                float2 o;
                o.x = acc[mi][ni][half * 2 + 0] + b0;
                o.y = acc[mi][ni][half * 2 + 1] + b1;
                *reinterpret_cast<float2*>(dst + col) = o;
            }
        }
    }
}

// =======================================================================
// mask / count
// =======================================================================
__global__ void mask_kernel(const unsigned int* __restrict__ bm)
{
    int n = blockIdx.x * blockDim.x + threadIdx.x;
    if (n >= NQ) return;
    int cnt = 0;
#pragma unroll
    for (int c = 0; c < CAMS; c++) {
        const unsigned int* q = bm + ((size_t)c * NQ + n) * DEPTH;
        unsigned int any = q[0] | q[1] | q[2] | q[3];
        int m = any ? 1 : 0;
        g_maskq[c * NQ + n] = m;
        cnt += m;
    }
    g_invcnt[n] = 1.0f / fmaxf((float)cnt, 1.0f);
}

// =======================================================================
// MSDA sampler, two-phase, softmax fused into phase 1:
//  phase1: warp h computes softmax over its 32 logits (shfl) and each
//          thread produces one sample's 4 clamped indices + 4 weights
//  phase2: warp h, split 16/16: lanes 0-15 even samples, 16-31 odd;
//          each lane loads bf16x2 (2 channels); shfl-combine at the end.
// =======================================================================
__global__ __launch_bounds__(256) void sampler_kernel(const float* __restrict__ refcam)
{
    const int bx = blockIdx.x;           // c*NQ + n
    const int c  = bx / NQ;
    const int n  = bx - c * NQ;
    __shared__ float sref[8];
    __shared__ int   smask;
    __shared__ int4   sidx[256];
    __shared__ float4 swt [256];

    const int tid = threadIdx.x;
    if (tid == 0) smask = g_maskq[bx];
    if (tid < 8) sref[tid] = refcam[(size_t)bx * 8 + tid];
    __syncthreads();
    if (!smask) {
        g_outcam[(size_t)bx * EMBED + tid] = __float2bfloat16(0.f);
        return;
    }

    // ---- phase 1: softmax + coordinates & weights (warp == head) ----
    {
        const int s = tid & 31;          // sample within head
        const int l = s >> 3;
        const int d = s & 3;
        const int   cWl[4] = {176, 88, 44, 22};
        const int   cHl[4] = {64, 32, 16, 8};
        const int   cls[4] = {0, 11264, 14080, 14784};
        const int Wl = cWl[l], Hl = cHl[l], ls = cls[l];

        float2 off   = *reinterpret_cast<const float2*>(g_offaw + (size_t)n * NOFFAW + 2 * tid);
        float  logit = g_offaw[(size_t)n * NOFFAW + 512 + tid];

        float m = logit;
#pragma unroll
        for (int o = 16; o; o >>= 1) m = fmaxf(m, __shfl_xor_sync(0xffffffffu, m, o));
        float e = __expf(logit - m);
        float ssum = e;
#pragma unroll
        for (int o = 16; o; o >>= 1) ssum += __shfl_xor_sync(0xffffffffu, ssum, o);
        float aw = e / ssum;

        float x = sref[d * 2 + 0] * (float)Wl + off.x - 0.5f;
        float y = sref[d * 2 + 1] * (float)Hl + off.y - 0.5f;
        float x0f = floorf(x), y0f = floorf(y);
        float fx = x - x0f, fy = y - y0f;
        int x0 = (int)x0f, y0 = (int)y0f;
        int x1 = x0 + 1,   y1 = y0 + 1;

        float vx0 = ((unsigned)x0 < (unsigned)Wl) ? 1.f : 0.f;
        float vx1 = ((unsigned)x1 < (unsigned)Wl) ? 1.f : 0.f;
        float vy0 = ((unsigned)y0 < (unsigned)Hl) ? 1.f : 0.f;
        float vy1 = ((unsigned)y1 < (unsigned)Hl) ? 1.f : 0.f;

        int cx0 = min(max(x0, 0), Wl - 1);
        int cx1 = min(max(x1, 0), Wl - 1);
        int cy0 = min(max(y0, 0), Hl - 1);
        int cy1 = min(max(y1, 0), Hl - 1);

        int4 id;
        id.x = ls + cy0 * Wl + cx0;
        id.y = ls + cy0 * Wl + cx1;
        id.z = ls + cy1 * Wl + cx0;
        id.w = ls + cy1 * Wl + cx1;
        float4 w;
        w.x = (1.f - fx) * (1.f - fy) * aw * vx0 * vy0;
        w.y = fx * (1.f - fy) * aw * vx1 * vy0;
        w.z = (1.f - fx) * fy * aw * vx0 * vy1;
        w.w = fx * fy * aw * vx1 * vy1;
        sidx[tid] = id;
        swt [tid] = w;
    }
    __syncthreads();

    // ---- phase 2: vectorized gather ----
    {
        const int h    = tid >> 5;
        const int lane = tid & 31;
        const int half = lane >> 4;      // 0: even samples, 1: odd samples
        const int ch2  = lane & 15;      // channel pair
        const uint16_t* vb = reinterpret_cast<const uint16_t*>(
            g_vproj + (size_t)c * FLEN * EMBED + h * DH + ch2 * 2);
        float ax = 0.f, ay = 0.f;
#pragma unroll 4
        for (int it = 0; it < 16; it++) {
            int s = it * 2 + half;
            int4   id = sidx[h * 32 + s];
            float4 w  = swt [h * 32 + s];
            __nv_bfloat162 v0 = *reinterpret_cast<const __nv_bfloat162*>(vb + (size_t)id.x * EMBED);
            __nv_bfloat162 v1 = *reinterpret_cast<const __nv_bfloat162*>(vb + (size_t)id.y * EMBED);
            __nv_bfloat162 v2 = *reinterpret_cast<const __nv_bfloat162*>(vb + (size_t)id.z * EMBED);
            __nv_bfloat162 v3 = *reinterpret_cast<const __nv_bfloat162*>(vb + (size_t)id.w * EMBED);
            ax = fmaf(w.x, __bfloat162float(v0.x), ax);
            ay = fmaf(w.x, __bfloat162float(v0.y), ay);
            ax = fmaf(w.y, __bfloat162float(v1.x), ax);
            ay = fmaf(w.y, __bfloat162float(v1.y), ay);
            ax = fmaf(w.z, __bfloat162float(v2.x), ax);
            ay = fmaf(w.z, __bfloat162float(v2.y), ay);
            ax = fmaf(w.w, __bfloat162float(v3.x), ax);
            ay = fmaf(w.w, __bfloat162float(v3.y), ay);
        }
        ax += __shfl_xor_sync(0xffffffffu, ax, 16);
        ay += __shfl_xor_sync(0xffffffffu, ay, 16);
        if (half == 0) {
            __nv_bfloat162 o;
            o.x = __float2bfloat16(ax);
            o.y = __float2bfloat16(ay);
            *reinterpret_cast<__nv_bfloat162*>(
                g_outcam + (size_t)bx * EMBED + h * DH + ch2 * 2) = o;
        }
    }
}

// =======================================================================
// GEMM 3 (final mma): A[r][k] = invcnt[r]*sum_c outcam[c][r][k] (bf16)
// out = A @ Wout + bout + query.  M=6400, N=256, K=256.
// =======================================================================
__global__ __launch_bounds__(256) void final_mma_kernel(
    const float* __restrict__ query, const float* __restrict__ Wout,
    const float* __restrict__ bout, float* __restrict__ out)
{
    extern __shared__ char smem[];
    __nv_bfloat16* Bs = reinterpret_cast<__nv_bfloat16*>(smem);
    __nv_bfloat16* As = reinterpret_cast<__nv_bfloat16*>(smem + 128 * BP * 2);

    const int tid  = threadIdx.x;
    const int wid  = tid >> 5;
    const int lane = tid & 31;
    const int wm   = wid >> 1;
    const int wn   = wid & 1;
    const int n0   = blockIdx.x * 128;
    const int row0 = blockIdx.y * 128;
    const int qr = lane >> 2, qc = lane & 3;

#pragma unroll
    for (int i = 0; i < 64; i++) {
        int u  = i * 256 + tid;
        int k  = u >> 6;
        int np = u & 63;
        float2 w = *reinterpret_cast<const float2*>(Wout + (size_t)k * EMBED + n0 + np * 2);
        Bs[(np * 2 + 0) * BP + k] = __float2bfloat16(w.x);
        Bs[(np * 2 + 1) * BP + k] = __float2bfloat16(w.y);
    }

    float acc[2][8][4];
#pragma unroll
    for (int mi = 0; mi < 2; mi++)
#pragma unroll
        for (int ni = 0; ni < 8; ni++)
#pragma unroll
            for (int j = 0; j < 4; j++) acc[mi][ni][j] = 0.f;

    for (int kc = 0; kc < 8; kc++) {
        __syncthreads();
#pragma unroll
        for (int i = 0; i < 4; i++) {
            int u   = i * 256 + tid;
            int row = u >> 3;
            int kq  = (u & 7) * 4;
            int r = row0 + row;
            float inv = g_invcnt[r];
            float s0 = 0.f, s1 = 0.f, s2 = 0.f, s3 = 0.f;
#pragma unroll
            for (int c = 0; c < CAMS; c++) {
                const __nv_bfloat16* src =
                    g_outcam + ((size_t)c * NQ + r) * EMBED + kc * 32 + kq;
                uint2 u2 = *reinterpret_cast<const uint2*>(src);
                __nv_bfloat162 p0 = *reinterpret_cast<__nv_bfloat162*>(&u2.x);
                __nv_bfloat162 p1 = *reinterpret_cast<__nv_bfloat162*>(&u2.y);
                s0 += __bfloat162float(p0.x); s1 += __bfloat162float(p0.y);
                s2 += __bfloat162float(p1.x); s3 += __bfloat162float(p1.y);
            }
            __nv_bfloat162 q0, q1;
            q0.x = __float2bfloat16(s0 * inv); q0.y = __float2bfloat16(s1 * inv);
            q1.x = __float2bfloat16(s2 * inv); q1.y = __float2bfloat16(s3 * inv);
            uint2 st;
            st.x = *reinterpret_cast<uint32_t*>(&q0);
            st.y = *reinterpret_cast<uint32_t*>(&q1);
            *reinterpret_cast<uint2*>(&As[row * AP + kq]) = st;
        }
        __syncthreads();
        mma_chunk(As, Bs, kc, wm, wn, qr, qc, acc);
    }

#pragma unroll
    for (int mi = 0; mi < 2; mi++) {
        int rb = row0 + wm * 32 + mi * 16;
#pragma unroll
        for (int half = 0; half < 2; half++) {
            int r = rb + qr + half * 8;
            float* dst = out + (size_t)r * EMBED;
            const float* qsrc = query + (size_t)r * EMBED;
#pragma unroll
            for (int ni = 0; ni < 8; ni++) {
                int n = n0 + wn * 64 + ni * 8 + qc * 2;
                float2 qv = *reinterpret_cast<const float2*>(qsrc + n);
                float2 o;
                o.x = acc[mi][ni][half * 2 + 0] + bout[n] + qv.x;
                o.y = acc[mi][ni][half * 2 + 1] + bout[n + 1] + qv.y;
                *reinterpret_cast<float2*>(dst + n) = o;
            }
        }
    }
}

// =======================================================================
extern "C" void kernel_launch(void* const* d_in, const int* in_sizes, int n_in,
                              void* d_out, int out_size)
{
    const float* query = (const float*)d_in[0];
    /* d_in[1] = key : unused by the reference */
    const float* value = (const float*)d_in[2];
    const float* qpos  = (const float*)d_in[3];
    const float* refc  = (const float*)d_in[4];
    const unsigned int* bmask = (const unsigned int*)d_in[5];
    /* d_in[6] spatial_shapes, d_in[7] level_start_index : compile-time constants */
    const float* Wv   = (const float*)d_in[8];
    const float* bv   = (const float*)d_in[9];
    const float* Wso  = (const float*)d_in[10];
    const float* bso  = (const float*)d_in[11];
    const float* Waw  = (const float*)d_in[12];
    const float* baw  = (const float*)d_in[13];
    const float* Wout = (const float*)d_in[14];
    const float* bout = (const float*)d_in[15];
    float* out = (float*)d_out;

    cudaFuncSetAttribute(vproj_mma_kernel,
                         cudaFuncAttributeMaxDynamicSharedMemorySize, VP_SMEM);
    cudaFuncSetAttribute(offaw_mma_kernel,
                         cudaFuncAttributeMaxDynamicSharedMemorySize, VP_SMEM);
    cudaFuncSetAttribute(final_mma_kernel,
                         cudaFuncAttributeMaxDynamicSharedMemorySize, VP_SMEM);

    vproj_mma_kernel<<<dim3(2, 702), 256, VP_SMEM>>>(value, Wv, bv);
    offaw_mma_kernel<<<dim3(6, 50), 256, VP_SMEM>>>(query, qpos, Wso, bso, Waw, baw);
    mask_kernel     <<<25, 256>>>(bmask);
    sampler_kernel  <<<CAMS * NQ, 256>>>(refc);
    final_mma_kernel<<<dim3(2, 50), 256, VP_SMEM>>>(query, Wout, bout, out);
}